// round 2
// baseline (speedup 1.0000x reference)
#include <cuda_runtime.h>
#include <cuda_bf16.h>

// Problem constants
#define NB   128      // N batch
#define LL   64       // L sequence
#define HH   512      // H hidden
#define EE   512      // E embed
#define NCELL 2080    // 64*65/2 triangular cells
#define CELLF 65536   // 128*512 floats per cell

// GEMM tiling
#define BM 64
#define BN 64
#define BK 16
#define NTHREADS 256
#define PAD 4   // shared row padding (keeps 16B alignment: 68*4B = 272B)

// Scratch (allocation-free: __device__ globals)
__device__ float g_H[(size_t)NCELL * CELLF];   // 545 MB: all H(s,k) cells, [128][512] each
__device__ float g_y[8192 * 512];              // 16 MB: output-layer logits (yflat, [L*N, E])
__device__ float g_part[NB];                   // per-n partial loss sums

__device__ __forceinline__ int cellidx(int s, int k) { return s * (s + 1) / 2 + k; }

// ---------------------------------------------------------------------------
// Phase 1: x = emb_table[labels] @ W_in^T + b_in   -> H(s,0)[n] = x[n,s,:]
// GEMM rows r = s*128 + n (A row gathered via labels[n,s]); M=8192,N=512,K=512
// ---------------------------------------------------------------------------
__global__ void __launch_bounds__(NTHREADS)
k_input(const int* __restrict__ labels, const float* __restrict__ emb_table,
        const float* __restrict__ W_in, const float* __restrict__ b_in)
{
    __shared__ float As[BK][BM + PAD];
    __shared__ float Ws[BK][BN + PAD];

    const int tid = threadIdx.x;
    const int tn = tid & 15, tm = tid >> 4;
    const int row0 = blockIdx.y * BM;
    const int col0 = blockIdx.x * BN;

    // per-thread load slot: (row rl, 4 consecutive k at ks)
    const int rl = tid >> 2;
    const int ks = (tid & 3) * 4;

    // A row pointer for this thread's load row
    const int rA = row0 + rl;
    const int nA = rA & 127, sA = rA >> 7;
    const float* arow = emb_table + (size_t)labels[nA * LL + sA] * EE;
    const float* wrow = W_in + (size_t)(col0 + rl) * EE;

    float acc[4][4] = {};

    for (int k0 = 0; k0 < EE; k0 += BK) {
        float4 av = *reinterpret_cast<const float4*>(arow + k0 + ks);
        float4 wv = *reinterpret_cast<const float4*>(wrow + k0 + ks);
        As[ks + 0][rl] = av.x; As[ks + 1][rl] = av.y;
        As[ks + 2][rl] = av.z; As[ks + 3][rl] = av.w;
        Ws[ks + 0][rl] = wv.x; Ws[ks + 1][rl] = wv.y;
        Ws[ks + 2][rl] = wv.z; Ws[ks + 3][rl] = wv.w;
        __syncthreads();
        #pragma unroll
        for (int kk = 0; kk < BK; ++kk) {
            float4 a4 = *reinterpret_cast<const float4*>(&As[kk][tm * 4]);
            float4 w4 = *reinterpret_cast<const float4*>(&Ws[kk][tn * 4]);
            float a[4] = {a4.x, a4.y, a4.z, a4.w};
            float w[4] = {w4.x, w4.y, w4.z, w4.w};
            #pragma unroll
            for (int i = 0; i < 4; ++i)
                #pragma unroll
                for (int j = 0; j < 4; ++j)
                    acc[i][j] += a[i] * w[j];
        }
        __syncthreads();
    }

    #pragma unroll
    for (int i = 0; i < 4; ++i) {
        int r = row0 + tm * 4 + i;
        int n = r & 127, s = r >> 7;
        float* out = g_H + (size_t)cellidx(s, 0) * CELLF + (size_t)n * HH + col0;
        #pragma unroll
        for (int j = 0; j < 4; ++j) {
            int c = tn * 4 + j;
            out[c] = acc[i][j] + b_in[col0 + c];
        }
    }
}

// ---------------------------------------------------------------------------
// Phase 2 (wavefront): H(s,k) = H(s-1,k-1)@W1^T + H(s,k-1)@W2^T + b_sani
// One launch per diagonal d = s+k; blockIdx.z enumerates cells on the diagonal.
// K=1024 (first 512 from A, second 512 from B). M=128, N=512.
// ---------------------------------------------------------------------------
__global__ void __launch_bounds__(NTHREADS)
k_wave(const float* __restrict__ W_sani, const float* __restrict__ b_sani,
       int d, int s_lo)
{
    const int s = s_lo + blockIdx.z;
    const int k = d - s;
    const float* A = g_H + (size_t)cellidx(s - 1, k - 1) * CELLF;
    const float* B = g_H + (size_t)cellidx(s,     k - 1) * CELLF;
    float*       C = g_H + (size_t)cellidx(s,     k    ) * CELLF;

    __shared__ float As[BK][BM + PAD];
    __shared__ float Ws[BK][BN + PAD];

    const int tid = threadIdx.x;
    const int tn = tid & 15, tm = tid >> 4;
    const int row0 = blockIdx.y * BM;
    const int col0 = blockIdx.x * BN;

    const int rl = tid >> 2;
    const int ks = (tid & 3) * 4;

    const float* wrow = W_sani + (size_t)(col0 + rl) * (2 * HH);

    float acc[4][4] = {};

    for (int k0 = 0; k0 < 2 * HH; k0 += BK) {
        const float* src = (k0 < HH) ? A : B;
        const int koff = (k0 < HH) ? k0 : (k0 - HH);
        float4 av = *reinterpret_cast<const float4*>(src + (size_t)(row0 + rl) * HH + koff + ks);
        float4 wv = *reinterpret_cast<const float4*>(wrow + k0 + ks);
        As[ks + 0][rl] = av.x; As[ks + 1][rl] = av.y;
        As[ks + 2][rl] = av.z; As[ks + 3][rl] = av.w;
        Ws[ks + 0][rl] = wv.x; Ws[ks + 1][rl] = wv.y;
        Ws[ks + 2][rl] = wv.z; Ws[ks + 3][rl] = wv.w;
        __syncthreads();
        #pragma unroll
        for (int kk = 0; kk < BK; ++kk) {
            float4 a4 = *reinterpret_cast<const float4*>(&As[kk][tm * 4]);
            float4 w4 = *reinterpret_cast<const float4*>(&Ws[kk][tn * 4]);
            float a[4] = {a4.x, a4.y, a4.z, a4.w};
            float w[4] = {w4.x, w4.y, w4.z, w4.w};
            #pragma unroll
            for (int i = 0; i < 4; ++i)
                #pragma unroll
                for (int j = 0; j < 4; ++j)
                    acc[i][j] += a[i] * w[j];
        }
        __syncthreads();
    }

    #pragma unroll
    for (int i = 0; i < 4; ++i) {
        int r = row0 + tm * 4 + i;
        float* out = C + (size_t)r * HH + col0;
        #pragma unroll
        for (int j = 0; j < 4; ++j) {
            int c = tn * 4 + j;
            out[c] = acc[i][j] + b_sani[col0 + c];
        }
    }
}

// ---------------------------------------------------------------------------
// Phase 3: yflat[r, :] = H(s,s)[n0, :] @ W_out^T + b_out,  r = s*128 + n0
// M=8192, N=512(E), K=512(H)
// ---------------------------------------------------------------------------
__global__ void __launch_bounds__(NTHREADS)
k_out(const float* __restrict__ W_out, const float* __restrict__ b_out)
{
    __shared__ float As[BK][BM + PAD];
    __shared__ float Ws[BK][BN + PAD];

    const int tid = threadIdx.x;
    const int tn = tid & 15, tm = tid >> 4;
    const int row0 = blockIdx.y * BM;
    const int col0 = blockIdx.x * BN;

    const int rl = tid >> 2;
    const int ks = (tid & 3) * 4;

    const int rA = row0 + rl;
    const int nA = rA & 127, sA = rA >> 7;
    const float* arow = g_H + (size_t)cellidx(sA, sA) * CELLF + (size_t)nA * HH;
    const float* wrow = W_out + (size_t)(col0 + rl) * HH;

    float acc[4][4] = {};

    for (int k0 = 0; k0 < HH; k0 += BK) {
        float4 av = *reinterpret_cast<const float4*>(arow + k0 + ks);
        float4 wv = *reinterpret_cast<const float4*>(wrow + k0 + ks);
        As[ks + 0][rl] = av.x; As[ks + 1][rl] = av.y;
        As[ks + 2][rl] = av.z; As[ks + 3][rl] = av.w;
        Ws[ks + 0][rl] = wv.x; Ws[ks + 1][rl] = wv.y;
        Ws[ks + 2][rl] = wv.z; Ws[ks + 3][rl] = wv.w;
        __syncthreads();
        #pragma unroll
        for (int kk = 0; kk < BK; ++kk) {
            float4 a4 = *reinterpret_cast<const float4*>(&As[kk][tm * 4]);
            float4 w4 = *reinterpret_cast<const float4*>(&Ws[kk][tn * 4]);
            float a[4] = {a4.x, a4.y, a4.z, a4.w};
            float w[4] = {w4.x, w4.y, w4.z, w4.w};
            #pragma unroll
            for (int i = 0; i < 4; ++i)
                #pragma unroll
                for (int j = 0; j < 4; ++j)
                    acc[i][j] += a[i] * w[j];
        }
        __syncthreads();
    }

    #pragma unroll
    for (int i = 0; i < 4; ++i) {
        int r = row0 + tm * 4 + i;
        float* out = g_y + (size_t)r * EE + col0;
        #pragma unroll
        for (int j = 0; j < 4; ++j) {
            int c = tn * 4 + j;
            out[c] = acc[i][j] + b_out[col0 + c];
        }
    }
}

// ---------------------------------------------------------------------------
// Phase 4: loss = -(1/(N*E)) * sum_{n,e} [ sum_l emb*y - (sum_l emb)*LSE_l(y) ]
// y[n,l,e] = g_y[(n*64+l)*512 + e]   (sequence-major reshape handled in phase 3)
// One block per n, 512 threads over e.
// ---------------------------------------------------------------------------
__global__ void __launch_bounds__(512)
k_loss(const int* __restrict__ labels, const float* __restrict__ emb_table)
{
    __shared__ float red[512];
    const int n = blockIdx.x;
    const int e = threadIdx.x;
    const float* yb = g_y + (size_t)n * LL * EE + e;

    float m = -1e30f;
    #pragma unroll
    for (int l = 0; l < LL; ++l) m = fmaxf(m, yb[(size_t)l * EE]);

    float se = 0.f, dot = 0.f, sume = 0.f;
    #pragma unroll
    for (int l = 0; l < LL; ++l) {
        float yv = yb[(size_t)l * EE];
        float ev = emb_table[(size_t)labels[n * LL + l] * EE + e];
        se   += expf(yv - m);
        dot  += ev * yv;
        sume += ev;
    }
    float lse = m + logf(se);
    red[e] = dot - sume * lse;
    __syncthreads();
    for (int stride = 256; stride > 0; stride >>= 1) {
        if (e < stride) red[e] += red[e + stride];
        __syncthreads();
    }
    if (e == 0) g_part[n] = red[0];
}

__global__ void k_final(float* __restrict__ out)
{
    __shared__ float red[128];
    const int t = threadIdx.x;
    red[t] = g_part[t];
    __syncthreads();
    for (int stride = 64; stride > 0; stride >>= 1) {
        if (t < stride) red[t] += red[t + stride];
        __syncthreads();
    }
    if (t == 0) out[0] = -red[0] / (float)(NB * EE);
}

// ---------------------------------------------------------------------------
extern "C" void kernel_launch(void* const* d_in, const int* in_sizes, int n_in,
                              void* d_out, int out_size)
{
    const int*   labels    = (const int*)  d_in[0];
    const float* emb_table = (const float*)d_in[1];
    const float* W_in      = (const float*)d_in[2];
    const float* b_in      = (const float*)d_in[3];
    const float* W_sani    = (const float*)d_in[4];
    const float* b_sani    = (const float*)d_in[5];
    const float* W_out     = (const float*)d_in[6];
    const float* b_out     = (const float*)d_in[7];

    dim3 thr(NTHREADS);

    // Phase 1: input conversion into H(s,0)
    k_input<<<dim3(EE / BN, 8192 / BM), thr>>>(labels, emb_table, W_in, b_in);

    // Phase 2: wavefront over diagonals d = s + k, k >= 1
    for (int d = 2; d <= 126; ++d) {
        int s_lo = (d + 1) / 2;
        if (d - 63 > s_lo) s_lo = d - 63;
        int s_hi = (d - 1 < 63) ? d - 1 : 63;
        int cells = s_hi - s_lo + 1;
        k_wave<<<dim3(HH / BN, NB / BM, cells), thr>>>(W_sani, b_sani, d, s_lo);
    }

    // Phase 3: output layer
    k_out<<<dim3(EE / BN, 8192 / BM), thr>>>(W_out, b_out);

    // Phase 4: softmax-CE loss (deterministic two-stage reduction)
    k_loss<<<NB, 512>>>(labels, emb_table);
    k_final<<<1, 128>>>((float*)d_out);
}

// round 9
// speedup vs baseline: 1.8734x; 1.8734x over previous
#include <cuda_runtime.h>
#include <cuda_bf16.h>
#include <cstdint>

// ---------------------------------------------------------------------------
// Problem constants
// ---------------------------------------------------------------------------
#define NB   128
#define LL   64
#define HH   512
#define EE   512
#define NCELL 2080
#define CELLF 65536   // 128*512

typedef __nv_bfloat16 bf16;

// GEMM config: CTA 128x128x32, 8 warps (2x4), warp tile 64x32
#define BKC   32                 // K per chunk (bf16)
#define RSB   80                 // smem row stride bytes (64 data + 16 pad)
#define TILE_B (128 * RSB)       // 10240 bytes per operand tile
#define STAGE_B (4 * TILE_B)     // Ahi, Alo, Whi, Wlo
#define GSMEM (2 * STAGE_B)      // 81920 bytes (double buffer)

// ---------------------------------------------------------------------------
// Device scratch (allocation-free)
// ---------------------------------------------------------------------------
__device__ bf16 g_Hhi[(size_t)NCELL * CELLF];    // 273 MB
__device__ bf16 g_Hlo[(size_t)NCELL * CELLF];    // 273 MB
__device__ bf16 g_Whi[HH * 2 * HH];              // W_sani hi
__device__ bf16 g_Wlo[HH * 2 * HH];
__device__ bf16 g_WinHi[HH * EE], g_WinLo[HH * EE];
__device__ bf16 g_WoutHi[EE * HH], g_WoutLo[EE * HH];
__device__ bf16 g_Xhi[8192 * EE], g_Xlo[8192 * EE];  // gathered embeddings
__device__ float g_y[8192 * 512];
__device__ float g_part[NB];

__device__ __forceinline__ int cellidx(int s, int k) { return s * (s + 1) / 2 + k; }

__device__ __forceinline__ uint32_t smem_u32(const void* p) {
    uint32_t a;
    asm("{ .reg .u64 t; cvta.to.shared.u64 t, %1; cvt.u32.u64 %0, t; }" : "=r"(a) : "l"(p));
    return a;
}

__device__ __forceinline__ void cpa16(uint32_t dst, const void* src) {
    asm volatile("cp.async.ca.shared.global [%0], [%1], 16;" :: "r"(dst), "l"(src));
}
__device__ __forceinline__ void cp_commit() {
    asm volatile("cp.async.commit_group;" ::: "memory");
}
__device__ __forceinline__ void cp_wait1() {
    asm volatile("cp.async.wait_group 1;" ::: "memory");
}
__device__ __forceinline__ void cp_wait0() {
    asm volatile("cp.async.wait_group 0;" ::: "memory");
}

__device__ __forceinline__ void mma16816(float c[4], uint32_t a0, uint32_t a1, uint32_t a2, uint32_t a3,
                                         uint32_t b0, uint32_t b1) {
    asm volatile(
        "mma.sync.aligned.m16n8k16.row.col.f32.bf16.bf16.f32 "
        "{%0,%1,%2,%3},{%4,%5,%6,%7},{%8,%9},{%0,%1,%2,%3};"
        : "+f"(c[0]), "+f"(c[1]), "+f"(c[2]), "+f"(c[3])
        : "r"(a0), "r"(a1), "r"(a2), "r"(a3), "r"(b0), "r"(b1));
}

// ---------------------------------------------------------------------------
// Shared GEMM body: C[128, n0:n0+128] = A[128,K] @ W[n0:n0+128, K]^T
// 3-product bf16 split (hi*hi + hi*lo + lo*hi), fp32 accum.
// A rows have lda = 512 elements; nchunks=32 -> K=1024 with A-source switch
// at chunk 16 (wave); nchunks=16 -> K=512.
// Epilogue: + bias[n0+col]; outF != nullptr -> fp32 store, else hi/lo split.
// ---------------------------------------------------------------------------
__device__ __forceinline__ void gemm_body(
    const bf16* __restrict__ aHiA, const bf16* __restrict__ aLoA,
    const bf16* __restrict__ aHiB, const bf16* __restrict__ aLoB,
    int nchunks,
    const bf16* __restrict__ wHi, const bf16* __restrict__ wLo, int ldw,
    int n0, const float* __restrict__ bias,
    bf16* __restrict__ outHi, bf16* __restrict__ outLo, float* __restrict__ outF)
{
    extern __shared__ __align__(128) char smem[];
    const uint32_t sbase = smem_u32(smem);
    const int tid = threadIdx.x;
    const int wid = tid >> 5, lane = tid & 31;
    const int wm = wid & 1, wn = wid >> 1;
    const int lr = lane >> 2;          // 0..7
    const int lc = (lane & 3) * 2;     // 0,2,4,6

    float acc[4][4][4];
    #pragma unroll
    for (int i = 0; i < 4; ++i)
        #pragma unroll
        for (int j = 0; j < 4; ++j)
            #pragma unroll
            for (int q = 0; q < 4; ++q) acc[i][j][q] = 0.f;

    // -- issue one stage of cp.async loads (chunk c -> buffer c&1) --
    auto issue = [&](int c) {
        const bf16* ah; const bf16* al; int ka;
        if (c < 16) { ah = aHiA; al = aLoA; ka = c * BKC; }
        else        { ah = aHiB; al = aLoB; ka = (c - 16) * BKC; }
        const int kw = c * BKC;
        const uint32_t sm = sbase + (uint32_t)(c & 1) * STAGE_B;
        #pragma unroll
        for (int i = 0; i < 2; ++i) {
            int ch = tid + i * 256;          // 0..511
            int row = ch >> 2, seg = ch & 3; // 4 x 16B per 64B data row
            uint32_t off = (uint32_t)(row * RSB + seg * 16);
            cpa16(sm + 0 * TILE_B + off, ah + (size_t)row * 512 + ka + seg * 8);
            cpa16(sm + 1 * TILE_B + off, al + (size_t)row * 512 + ka + seg * 8);
            cpa16(sm + 2 * TILE_B + off, wHi + (size_t)(n0 + row) * ldw + kw + seg * 8);
            cpa16(sm + 3 * TILE_B + off, wLo + (size_t)(n0 + row) * ldw + kw + seg * 8);
        }
        cp_commit();
    };

    issue(0);
    if (nchunks > 1) issue(1);

    for (int c = 0; c < nchunks; ++c) {
        if (c + 1 < nchunks) cp_wait1(); else cp_wait0();
        __syncthreads();

        const char* st = smem + (size_t)(c & 1) * STAGE_B;
        #pragma unroll
        for (int ks = 0; ks < 2; ++ks) {
            const int k0 = ks * 16;
            // B fragments (Whi / Wlo): reg = {W[nrow][k0+lc], W[nrow][k0+lc+1]}
            uint32_t bh[4][2], bl[4][2];
            #pragma unroll
            for (int ni = 0; ni < 4; ++ni) {
                const int nrow = wn * 32 + ni * 8 + lr;
                const char* ph = st + 2 * TILE_B + nrow * RSB + (k0 + lc) * 2;
                bh[ni][0] = *(const uint32_t*)ph;
                bh[ni][1] = *(const uint32_t*)(ph + 16);
                const char* pl = st + 3 * TILE_B + nrow * RSB + (k0 + lc) * 2;
                bl[ni][0] = *(const uint32_t*)pl;
                bl[ni][1] = *(const uint32_t*)(pl + 16);
            }
            #pragma unroll
            for (int mi = 0; mi < 4; ++mi) {
                const int mrow = wm * 64 + mi * 16 + lr;
                const char* ph = st + 0 * TILE_B + mrow * RSB + (k0 + lc) * 2;
                uint32_t a0 = *(const uint32_t*)ph;
                uint32_t a1 = *(const uint32_t*)(ph + 8 * RSB);
                uint32_t a2 = *(const uint32_t*)(ph + 16);
                uint32_t a3 = *(const uint32_t*)(ph + 8 * RSB + 16);
                const char* pl = st + 1 * TILE_B + mrow * RSB + (k0 + lc) * 2;
                uint32_t l0 = *(const uint32_t*)pl;
                uint32_t l1 = *(const uint32_t*)(pl + 8 * RSB);
                uint32_t l2 = *(const uint32_t*)(pl + 16);
                uint32_t l3 = *(const uint32_t*)(pl + 8 * RSB + 16);
                #pragma unroll
                for (int ni = 0; ni < 4; ++ni) {
                    mma16816(acc[mi][ni], a0, a1, a2, a3, bh[ni][0], bh[ni][1]);
                    mma16816(acc[mi][ni], a0, a1, a2, a3, bl[ni][0], bl[ni][1]);
                    mma16816(acc[mi][ni], l0, l1, l2, l3, bh[ni][0], bh[ni][1]);
                }
            }
        }
        __syncthreads();
        if (c + 2 < nchunks) issue(c + 2);
    }

    // -- epilogue --
    #pragma unroll
    for (int mi = 0; mi < 4; ++mi) {
        const int r0 = wm * 64 + mi * 16 + lr;
        #pragma unroll
        for (int ni = 0; ni < 4; ++ni) {
            const int ccol = wn * 32 + ni * 8 + lc;
            const float bx = bias[n0 + ccol];
            const float by = bias[n0 + ccol + 1];
            #pragma unroll
            for (int half = 0; half < 2; ++half) {
                const int r = r0 + half * 8;
                const float v0 = acc[mi][ni][half * 2]     + bx;
                const float v1 = acc[mi][ni][half * 2 + 1] + by;
                if (outF) {
                    float2 fv; fv.x = v0; fv.y = v1;
                    *reinterpret_cast<float2*>(outF + (size_t)r * 512 + n0 + ccol) = fv;
                } else {
                    bf16 h0 = __float2bfloat16(v0), h1 = __float2bfloat16(v1);
                    bf16 e0 = __float2bfloat16(v0 - __bfloat162float(h0));
                    bf16 e1 = __float2bfloat16(v1 - __bfloat162float(h1));
                    __nv_bfloat162 hp; hp.x = h0; hp.y = h1;
                    __nv_bfloat162 lp; lp.x = e0; lp.y = e1;
                    *reinterpret_cast<__nv_bfloat162*>(outHi + (size_t)r * 512 + n0 + ccol) = hp;
                    *reinterpret_cast<__nv_bfloat162*>(outLo + (size_t)r * 512 + n0 + ccol) = lp;
                }
            }
        }
    }
}

// ---------------------------------------------------------------------------
// Kernel wrappers
// ---------------------------------------------------------------------------
// Wave: H(s,k) = H(s-1,k-1)@W1^T + H(s,k-1)@W2^T + b_sani
__global__ void __launch_bounds__(256, 1)
k_wave(const float* __restrict__ b_sani, int d, int s_lo)
{
    const int s = s_lo + blockIdx.y;
    const int k = d - s;
    const size_t oA = (size_t)cellidx(s - 1, k - 1) * CELLF;
    const size_t oB = (size_t)cellidx(s,     k - 1) * CELLF;
    const size_t oC = (size_t)cellidx(s,     k    ) * CELLF;
    gemm_body(g_Hhi + oA, g_Hlo + oA, g_Hhi + oB, g_Hlo + oB, 32,
              g_Whi, g_Wlo, 2 * HH, blockIdx.x * 128, b_sani,
              g_Hhi + oC, g_Hlo + oC, nullptr);
}

// Input layer: cell(s,0) = X[s*128.., :] @ W_in^T + b_in
__global__ void __launch_bounds__(256, 1)
k_in(const float* __restrict__ b_in)
{
    const int s = blockIdx.y;   // m-tile == sequence step
    const size_t oC = (size_t)cellidx(s, 0) * CELLF;
    gemm_body(g_Xhi + (size_t)s * 128 * EE, g_Xlo + (size_t)s * 128 * EE,
              nullptr, nullptr, 16,
              g_WinHi, g_WinLo, EE, blockIdx.x * 128, b_in,
              g_Hhi + oC, g_Hlo + oC, nullptr);
}

// Output layer: y[s*128.., :] = H(s,s) @ W_out^T + b_out  (fp32 logits)
__global__ void __launch_bounds__(256, 1)
k_outp(const float* __restrict__ b_out)
{
    const int s = blockIdx.y;
    const size_t oA = (size_t)cellidx(s, s) * CELLF;
    gemm_body(g_Hhi + oA, g_Hlo + oA, nullptr, nullptr, 16,
              g_WoutHi, g_WoutLo, HH, blockIdx.x * 128, b_out,
              nullptr, nullptr, g_y + (size_t)s * 128 * 512);
}

// ---------------------------------------------------------------------------
// Prep kernels (reference device globals directly; no symbol-address lookups)
// ---------------------------------------------------------------------------
__global__ void k_split_sani(const float* __restrict__ src) {
    int i = blockIdx.x * blockDim.x + threadIdx.x;   // 524288
    float v = src[i];
    bf16 h = __float2bfloat16(v);
    g_Whi[i] = h;
    g_Wlo[i] = __float2bfloat16(v - __bfloat162float(h));
}
__global__ void k_split_in(const float* __restrict__ src) {
    int i = blockIdx.x * blockDim.x + threadIdx.x;   // 262144
    float v = src[i];
    bf16 h = __float2bfloat16(v);
    g_WinHi[i] = h;
    g_WinLo[i] = __float2bfloat16(v - __bfloat162float(h));
}
__global__ void k_split_out(const float* __restrict__ src) {
    int i = blockIdx.x * blockDim.x + threadIdx.x;   // 262144
    float v = src[i];
    bf16 h = __float2bfloat16(v);
    g_WoutHi[i] = h;
    g_WoutLo[i] = __float2bfloat16(v - __bfloat162float(h));
}

__global__ void __launch_bounds__(256)
k_gather(const int* __restrict__ labels, const float* __restrict__ emb)
{
    const int r = blockIdx.x;            // 0..8191, r = s*128 + n
    const int n = r & 127, s = r >> 7;
    const float* row = emb + (size_t)labels[n * LL + s] * EE;
    const int e = threadIdx.x * 2;
    float2 v = *reinterpret_cast<const float2*>(row + e);
    bf16 h0 = __float2bfloat16(v.x), h1 = __float2bfloat16(v.y);
    bf16 l0 = __float2bfloat16(v.x - __bfloat162float(h0));
    bf16 l1 = __float2bfloat16(v.y - __bfloat162float(h1));
    __nv_bfloat162 hp; hp.x = h0; hp.y = h1;
    __nv_bfloat162 lp; lp.x = l0; lp.y = l1;
    *reinterpret_cast<__nv_bfloat162*>(g_Xhi + (size_t)r * EE + e) = hp;
    *reinterpret_cast<__nv_bfloat162*>(g_Xlo + (size_t)r * EE + e) = lp;
}

// ---------------------------------------------------------------------------
// Loss: softmax-CE over axis L. Flat row r = s*128+n matches the reference
// concat(outputStates) layout; reshape(N,L,E) reads flat row (n*64+l), so
// y[n,l,e] = g_y[(n*64+l)*512 + e].
// ---------------------------------------------------------------------------
__global__ void __launch_bounds__(512)
k_loss(const int* __restrict__ labels, const float* __restrict__ emb_table)
{
    __shared__ float red[512];
    const int n = blockIdx.x;
    const int e = threadIdx.x;
    const float* yb = g_y + (size_t)n * LL * EE + e;

    float m = -1e30f;
    #pragma unroll
    for (int l = 0; l < LL; ++l) m = fmaxf(m, yb[(size_t)l * EE]);

    float se = 0.f, dot = 0.f, sume = 0.f;
    #pragma unroll
    for (int l = 0; l < LL; ++l) {
        float yv = yb[(size_t)l * EE];
        float ev = emb_table[(size_t)labels[n * LL + l] * EE + e];
        se   += expf(yv - m);
        dot  += ev * yv;
        sume += ev;
    }
    float lse = m + logf(se);
    red[e] = dot - sume * lse;
    __syncthreads();
    for (int stride = 256; stride > 0; stride >>= 1) {
        if (e < stride) red[e] += red[e + stride];
        __syncthreads();
    }
    if (e == 0) g_part[n] = red[0];
}

__global__ void k_final(float* __restrict__ out)
{
    __shared__ float red[128];
    const int t = threadIdx.x;
    red[t] = g_part[t];
    __syncthreads();
    for (int stride = 64; stride > 0; stride >>= 1) {
        if (t < stride) red[t] += red[t + stride];
        __syncthreads();
    }
    if (t == 0) out[0] = -red[0] / (float)(NB * EE);
}

// ---------------------------------------------------------------------------
extern "C" void kernel_launch(void* const* d_in, const int* in_sizes, int n_in,
                              void* d_out, int out_size)
{
    const int*   labels    = (const int*)  d_in[0];
    const float* emb_table = (const float*)d_in[1];
    const float* W_in      = (const float*)d_in[2];
    const float* b_in      = (const float*)d_in[3];
    const float* W_sani    = (const float*)d_in[4];
    const float* b_sani    = (const float*)d_in[5];
    const float* W_out     = (const float*)d_in[6];
    const float* b_out     = (const float*)d_in[7];

    // Unconditional every call (no static guards; deterministic). Idempotent,
    // non-stream API — legal during graph capture (same pattern as the R2
    // kernel that passed).
    cudaFuncSetAttribute(k_wave, cudaFuncAttributeMaxDynamicSharedMemorySize, GSMEM);
    cudaFuncSetAttribute(k_in,   cudaFuncAttributeMaxDynamicSharedMemorySize, GSMEM);
    cudaFuncSetAttribute(k_outp, cudaFuncAttributeMaxDynamicSharedMemorySize, GSMEM);

    // Phase 0: split weights to bf16 hi/lo
    k_split_sani<<<2048, 256>>>(W_sani);
    k_split_in<<<1024, 256>>>(W_in);
    k_split_out<<<1024, 256>>>(W_out);

    // Phase 0b: gather + split embeddings
    k_gather<<<8192, 256>>>(labels, emb_table);

    // Phase 1: input layer -> H(s,0)
    k_in<<<dim3(4, 64), 256, GSMEM>>>(b_in);

    // Phase 2: wavefront over diagonals d = s + k
    for (int d = 2; d <= 126; ++d) {
        int s_lo = (d + 1) / 2;
        if (d - 63 > s_lo) s_lo = d - 63;
        int s_hi = (d - 1 < 63) ? d - 1 : 63;
        int cells = s_hi - s_lo + 1;
        k_wave<<<dim3(4, cells), 256, GSMEM>>>(b_sani, d, s_lo);
    }

    // Phase 3: output layer -> g_y
    k_outp<<<dim3(4, 64), 256, GSMEM>>>(b_out);

    // Phase 4: loss
    k_loss<<<NB, 512>>>(labels, emb_table);
    k_final<<<1, 128>>>((float*)d_out);
}

// round 10
// speedup vs baseline: 2.2917x; 1.2233x over previous
#include <cuda_runtime.h>
#include <cuda_bf16.h>
#include <cstdint>

// ---------------------------------------------------------------------------
// Problem constants
// ---------------------------------------------------------------------------
#define NB   128
#define LL   64
#define HH   512
#define EE   512
#define NCELL 2080
#define CELLF 65536   // 128*512

typedef __nv_bfloat16 bf16;

// Tile config: each task = 64(M) x 64(N), K full. 16 tiles per logical cell
// (2 M-halves x 8 N-slices). 8 warps: 2(m) x 4(n), warp tile 32x16.
#define RSB    80                 // smem row stride bytes (64 data + 16 pad)
#define TILE_B (64 * RSB)         // 5120 bytes per operand tile
#define STAGE_B (4 * TILE_B)      // Ahi, Alo, Whi, Wlo = 20480
// total static smem = 2 * STAGE_B = 40960 (< 48KB, no attribute needed)

#define NLCELL 2144               // 64 input + 2016 wave + 64 output
#define NTASK  (NLCELL * 16)
#define NCTA   148

// ---------------------------------------------------------------------------
// Device scratch (allocation-free)
// ---------------------------------------------------------------------------
__device__ bf16 g_Hhi[(size_t)NCELL * CELLF];
__device__ bf16 g_Hlo[(size_t)NCELL * CELLF];
__device__ bf16 g_Whi[HH * 2 * HH], g_Wlo[HH * 2 * HH];
__device__ bf16 g_WinHi[HH * EE],  g_WinLo[HH * EE];
__device__ bf16 g_WoutHi[EE * HH], g_WoutLo[EE * HH];
__device__ bf16 g_Xhi[8192 * EE],  g_Xlo[8192 * EE];
__device__ float g_y[8192 * 512];
__device__ float g_part[NB];

// Scheduling state
__device__ int  g_next;
__device__ int  g_done[NCELL];     // completed-tile count per cell (16 = ready)
__device__ int2 g_list[NCELL];     // wave cell list entries [64, 2080)

__device__ __forceinline__ int cellidx(int s, int k) { return s * (s + 1) / 2 + k; }

__device__ __forceinline__ uint32_t smem_u32(const void* p) {
    uint32_t a;
    asm("{ .reg .u64 t; cvta.to.shared.u64 t, %1; cvt.u32.u64 %0, t; }" : "=r"(a) : "l"(p));
    return a;
}
__device__ __forceinline__ void cpa16(uint32_t dst, const void* src) {
    asm volatile("cp.async.ca.shared.global [%0], [%1], 16;" :: "r"(dst), "l"(src));
}
__device__ __forceinline__ void cp_commit() { asm volatile("cp.async.commit_group;" ::: "memory"); }
__device__ __forceinline__ void cp_wait1()  { asm volatile("cp.async.wait_group 1;" ::: "memory"); }
__device__ __forceinline__ void cp_wait0()  { asm volatile("cp.async.wait_group 0;" ::: "memory"); }

__device__ __forceinline__ int ld_acq(const int* p) {
    int v;
    asm volatile("ld.acquire.gpu.global.b32 %0, [%1];" : "=r"(v) : "l"(p));
    return v;
}
__device__ __forceinline__ void red_rel(int* p) {
    asm volatile("red.release.gpu.global.add.s32 [%0], 1;" :: "l"(p));
}

__device__ __forceinline__ void mma16816(float c[4], uint32_t a0, uint32_t a1, uint32_t a2, uint32_t a3,
                                         uint32_t b0, uint32_t b1) {
    asm volatile(
        "mma.sync.aligned.m16n8k16.row.col.f32.bf16.bf16.f32 "
        "{%0,%1,%2,%3},{%4,%5,%6,%7},{%8,%9},{%0,%1,%2,%3};"
        : "+f"(c[0]), "+f"(c[1]), "+f"(c[2]), "+f"(c[3])
        : "r"(a0), "r"(a1), "r"(a2), "r"(a3), "r"(b0), "r"(b1));
}

// ---------------------------------------------------------------------------
// Init: zero flags, reset counter, build wave cell list (diagonal order)
// ---------------------------------------------------------------------------
__global__ void k_init()
{
    int i = blockIdx.x * blockDim.x + threadIdx.x;
    if (i < NCELL) g_done[i] = 0;
    if (i == 0) g_next = 0;
    if (i == 1) {
        int idx = 64;
        for (int d = 2; d <= 126; ++d) {
            int s_lo = (d + 1) / 2;
            if (d - 63 > s_lo) s_lo = d - 63;
            int s_hi = (d - 1 < 63) ? d - 1 : 63;
            for (int s = s_lo; s <= s_hi; ++s)
                g_list[idx++] = make_int2(s, d - s);
        }
    }
}

// ---------------------------------------------------------------------------
// Persistent SANI kernel: dependency-driven task loop over all GEMM tiles.
// Task t: lc = t>>4 (logical cell), tile = t&15 -> mh = tile&1, ns = tile>>1.
//   lc <   64 : input  tile  cell(s=lc, 0)   = X[s] @ W_in^T + b_in
//   lc < 2080 : wave   tile  cell(s,k)       = A1@W1^T + A2@W2^T + b_sani
//   else      : output tile  y[s] rows       = H(s,s) @ W_out^T + b_out
// ---------------------------------------------------------------------------
__global__ void __launch_bounds__(256, 1)
k_sani(const float* __restrict__ b_in, const float* __restrict__ b_sani,
       const float* __restrict__ b_out)
{
    __shared__ __align__(128) char smem[2 * STAGE_B];
    __shared__ int sh_task;

    const uint32_t sbase = smem_u32(smem);
    const int tid = threadIdx.x;
    const int wid = tid >> 5, lane = tid & 31;
    const int wm = wid & 1, wn = wid >> 1;       // warp grid 2(m) x 4(n)
    const int lr = lane >> 2;                    // 0..7
    const int lc2 = (lane & 3) * 2;              // 0,2,4,6

    for (;;) {
        if (tid == 0) sh_task = atomicAdd(&g_next, 1);
        __syncthreads();
        const int t = sh_task;
        __syncthreads();          // protect sh_task before next iteration's write
        if (t >= NTASK) return;

        const int lcell = t >> 4;
        const int tile  = t & 15;
        const int mh = tile & 1;                 // M-half (64 rows)
        const int n0 = (tile >> 1) * 64;         // N-slice base (0..448)

        int type, s, k = 0;
        if (lcell < 64)        { type = 0; s = lcell; }
        else if (lcell < 2080) { type = 1; int2 c = g_list[lcell]; s = c.x; k = c.y; }
        else                   { type = 2; s = lcell - 2080; }

        // ---- dependency wait (thread 0 polls, barrier broadcasts) ----
        if (tid == 0) {
            if (type == 1) {
                const int* p1 = &g_done[cellidx(s - 1, k - 1)];
                const int* p2 = &g_done[cellidx(s,     k - 1)];
                while (ld_acq(p1) < 16) __nanosleep(64);
                while (ld_acq(p2) < 16) __nanosleep(64);
            } else if (type == 2) {
                const int* p = &g_done[cellidx(s, s)];
                while (ld_acq(p) < 16) __nanosleep(64);
            }
        }
        __syncthreads();

        // ---- operand pointers ----
        const bf16 *aH1, *aL1, *aH2 = nullptr, *aL2 = nullptr, *wH, *wL;
        const float* bias;
        int ldw, nch;
        size_t rowbase = (size_t)mh * 64 * 512;
        if (type == 0) {
            size_t xb = (size_t)s * 128 * 512 + rowbase;
            aH1 = g_Xhi + xb;  aL1 = g_Xlo + xb;
            wH = g_WinHi + (size_t)n0 * 512;  wL = g_WinLo + (size_t)n0 * 512;
            ldw = 512; nch = 16; bias = b_in;
        } else if (type == 1) {
            size_t pa = (size_t)cellidx(s - 1, k - 1) * CELLF + rowbase;
            size_t pb = (size_t)cellidx(s,     k - 1) * CELLF + rowbase;
            aH1 = g_Hhi + pa;  aL1 = g_Hlo + pa;
            aH2 = g_Hhi + pb;  aL2 = g_Hlo + pb;
            wH = g_Whi + (size_t)n0 * 1024;  wL = g_Wlo + (size_t)n0 * 1024;
            ldw = 1024; nch = 32; bias = b_sani;
        } else {
            size_t pa = (size_t)cellidx(s, s) * CELLF + rowbase;
            aH1 = g_Hhi + pa;  aL1 = g_Hlo + pa;
            wH = g_WoutHi + (size_t)n0 * 512;  wL = g_WoutLo + (size_t)n0 * 512;
            ldw = 512; nch = 16; bias = b_out;
        }

        // ---- GEMM: 64x64, K = nch*32, 3-product bf16 split ----
        float acc[2][2][4];
        #pragma unroll
        for (int i = 0; i < 2; ++i)
            #pragma unroll
            for (int j = 0; j < 2; ++j)
                #pragma unroll
                for (int q = 0; q < 4; ++q) acc[i][j][q] = 0.f;

        auto issue = [&](int c) {
            const bf16* ah; const bf16* al; int ka;
            if (c < 16) { ah = aH1; al = aL1; ka = c * 32; }
            else        { ah = aH2; al = aL2; ka = (c - 16) * 32; }
            const int kw = c * 32;
            const uint32_t sm = sbase + (uint32_t)(c & 1) * STAGE_B;
            const int row = tid >> 2, seg = tid & 3;
            const uint32_t off = (uint32_t)(row * RSB + seg * 16);
            cpa16(sm + 0 * TILE_B + off, ah + (size_t)row * 512 + ka + seg * 8);
            cpa16(sm + 1 * TILE_B + off, al + (size_t)row * 512 + ka + seg * 8);
            cpa16(sm + 2 * TILE_B + off, wH + (size_t)row * ldw + kw + seg * 8);
            cpa16(sm + 3 * TILE_B + off, wL + (size_t)row * ldw + kw + seg * 8);
            cp_commit();
        };

        issue(0);
        issue(1);

        for (int c = 0; c < nch; ++c) {
            if (c + 1 < nch) cp_wait1(); else cp_wait0();
            __syncthreads();

            const char* st = smem + (size_t)(c & 1) * STAGE_B;
            #pragma unroll
            for (int ks = 0; ks < 2; ++ks) {
                const int k0 = ks * 16;
                uint32_t bh[2][2], bl[2][2];
                #pragma unroll
                for (int ni = 0; ni < 2; ++ni) {
                    const int nrow = wn * 16 + ni * 8 + lr;
                    const char* ph = st + 2 * TILE_B + nrow * RSB + (k0 + lc2) * 2;
                    bh[ni][0] = *(const uint32_t*)ph;
                    bh[ni][1] = *(const uint32_t*)(ph + 16);
                    const char* pl = st + 3 * TILE_B + nrow * RSB + (k0 + lc2) * 2;
                    bl[ni][0] = *(const uint32_t*)pl;
                    bl[ni][1] = *(const uint32_t*)(pl + 16);
                }
                #pragma unroll
                for (int mi = 0; mi < 2; ++mi) {
                    const int mrow = wm * 32 + mi * 16 + lr;
                    const char* ph = st + 0 * TILE_B + mrow * RSB + (k0 + lc2) * 2;
                    uint32_t a0 = *(const uint32_t*)ph;
                    uint32_t a1 = *(const uint32_t*)(ph + 8 * RSB);
                    uint32_t a2 = *(const uint32_t*)(ph + 16);
                    uint32_t a3 = *(const uint32_t*)(ph + 8 * RSB + 16);
                    const char* pl = st + 1 * TILE_B + mrow * RSB + (k0 + lc2) * 2;
                    uint32_t l0 = *(const uint32_t*)pl;
                    uint32_t l1 = *(const uint32_t*)(pl + 8 * RSB);
                    uint32_t l2 = *(const uint32_t*)(pl + 16);
                    uint32_t l3 = *(const uint32_t*)(pl + 8 * RSB + 16);
                    #pragma unroll
                    for (int ni = 0; ni < 2; ++ni) {
                        mma16816(acc[mi][ni], a0, a1, a2, a3, bh[ni][0], bh[ni][1]);
                        mma16816(acc[mi][ni], a0, a1, a2, a3, bl[ni][0], bl[ni][1]);
                        mma16816(acc[mi][ni], l0, l1, l2, l3, bh[ni][0], bh[ni][1]);
                    }
                }
            }
            __syncthreads();
            if (c + 2 < nch) issue(c + 2);
        }

        // ---- epilogue ----
        int dstCell = (type == 0) ? cellidx(s, 0) : (type == 1 ? cellidx(s, k) : -1);
        bf16* outHi = (dstCell >= 0) ? g_Hhi + (size_t)dstCell * CELLF : nullptr;
        bf16* outLo = (dstCell >= 0) ? g_Hlo + (size_t)dstCell * CELLF : nullptr;
        float* outF = (type == 2) ? g_y + (size_t)s * 128 * 512 : nullptr;

        #pragma unroll
        for (int mi = 0; mi < 2; ++mi) {
            const int r0 = mh * 64 + wm * 32 + mi * 16 + lr;   // row within 128
            #pragma unroll
            for (int ni = 0; ni < 2; ++ni) {
                const int ccol = n0 + wn * 16 + ni * 8 + lc2;
                const float bx = bias[ccol];
                const float by = bias[ccol + 1];
                #pragma unroll
                for (int half = 0; half < 2; ++half) {
                    const int r = r0 + half * 8;
                    const float v0 = acc[mi][ni][half * 2]     + bx;
                    const float v1 = acc[mi][ni][half * 2 + 1] + by;
                    if (outF) {
                        float2 fv; fv.x = v0; fv.y = v1;
                        *reinterpret_cast<float2*>(outF + (size_t)r * 512 + ccol) = fv;
                    } else {
                        bf16 h0 = __float2bfloat16(v0), h1 = __float2bfloat16(v1);
                        bf16 e0 = __float2bfloat16(v0 - __bfloat162float(h0));
                        bf16 e1 = __float2bfloat16(v1 - __bfloat162float(h1));
                        __nv_bfloat162 hp; hp.x = h0; hp.y = h1;
                        __nv_bfloat162 lp; lp.x = e0; lp.y = e1;
                        *reinterpret_cast<__nv_bfloat162*>(outHi + (size_t)r * 512 + ccol) = hp;
                        *reinterpret_cast<__nv_bfloat162*>(outLo + (size_t)r * 512 + ccol) = lp;
                    }
                }
            }
        }

        // ---- signal completion ----
        if (dstCell >= 0) {
            __threadfence();
            __syncthreads();
            if (tid == 0) red_rel(&g_done[dstCell]);
        }
    }
}

// ---------------------------------------------------------------------------
// Prep kernels
// ---------------------------------------------------------------------------
__global__ void k_split_sani(const float* __restrict__ src) {
    int i = blockIdx.x * blockDim.x + threadIdx.x;
    float v = src[i];
    bf16 h = __float2bfloat16(v);
    g_Whi[i] = h;
    g_Wlo[i] = __float2bfloat16(v - __bfloat162float(h));
}
__global__ void k_split_in(const float* __restrict__ src) {
    int i = blockIdx.x * blockDim.x + threadIdx.x;
    float v = src[i];
    bf16 h = __float2bfloat16(v);
    g_WinHi[i] = h;
    g_WinLo[i] = __float2bfloat16(v - __bfloat162float(h));
}
__global__ void k_split_out(const float* __restrict__ src) {
    int i = blockIdx.x * blockDim.x + threadIdx.x;
    float v = src[i];
    bf16 h = __float2bfloat16(v);
    g_WoutHi[i] = h;
    g_WoutLo[i] = __float2bfloat16(v - __bfloat162float(h));
}

__global__ void __launch_bounds__(256)
k_gather(const int* __restrict__ labels, const float* __restrict__ emb)
{
    const int r = blockIdx.x;            // r = s*128 + n
    const int n = r & 127, s = r >> 7;
    const float* row = emb + (size_t)labels[n * LL + s] * EE;
    const int e = threadIdx.x * 2;
    float2 v = *reinterpret_cast<const float2*>(row + e);
    bf16 h0 = __float2bfloat16(v.x), h1 = __float2bfloat16(v.y);
    bf16 l0 = __float2bfloat16(v.x - __bfloat162float(h0));
    bf16 l1 = __float2bfloat16(v.y - __bfloat162float(h1));
    __nv_bfloat162 hp; hp.x = h0; hp.y = h1;
    __nv_bfloat162 lp; lp.x = l0; lp.y = l1;
    *reinterpret_cast<__nv_bfloat162*>(g_Xhi + (size_t)r * EE + e) = hp;
    *reinterpret_cast<__nv_bfloat162*>(g_Xlo + (size_t)r * EE + e) = lp;
}

// ---------------------------------------------------------------------------
// Loss (flat row r = s*128+n; reshape(N,L,E) reads flat row n*64+l)
// ---------------------------------------------------------------------------
__global__ void __launch_bounds__(512)
k_loss(const int* __restrict__ labels, const float* __restrict__ emb_table)
{
    __shared__ float red[512];
    const int n = blockIdx.x;
    const int e = threadIdx.x;
    const float* yb = g_y + (size_t)n * LL * EE + e;

    float m = -1e30f;
    #pragma unroll
    for (int l = 0; l < LL; ++l) m = fmaxf(m, yb[(size_t)l * EE]);

    float se = 0.f, dot = 0.f, sume = 0.f;
    #pragma unroll
    for (int l = 0; l < LL; ++l) {
        float yv = yb[(size_t)l * EE];
        float ev = emb_table[(size_t)labels[n * LL + l] * EE + e];
        se   += expf(yv - m);
        dot  += ev * yv;
        sume += ev;
    }
    float lse = m + logf(se);
    red[e] = dot - sume * lse;
    __syncthreads();
    for (int stride = 256; stride > 0; stride >>= 1) {
        if (e < stride) red[e] += red[e + stride];
        __syncthreads();
    }
    if (e == 0) g_part[n] = red[0];
}

__global__ void k_final(float* __restrict__ out)
{
    __shared__ float red[128];
    const int t = threadIdx.x;
    red[t] = g_part[t];
    __syncthreads();
    for (int stride = 64; stride > 0; stride >>= 1) {
        if (t < stride) red[t] += red[t + stride];
        __syncthreads();
    }
    if (t == 0) out[0] = -red[0] / (float)(NB * EE);
}

// ---------------------------------------------------------------------------
extern "C" void kernel_launch(void* const* d_in, const int* in_sizes, int n_in,
                              void* d_out, int out_size)
{
    const int*   labels    = (const int*)  d_in[0];
    const float* emb_table = (const float*)d_in[1];
    const float* W_in      = (const float*)d_in[2];
    const float* b_in      = (const float*)d_in[3];
    const float* W_sani    = (const float*)d_in[4];
    const float* b_sani    = (const float*)d_in[5];
    const float* W_out     = (const float*)d_in[6];
    const float* b_out     = (const float*)d_in[7];

    // Scheduling state reset + task list build
    k_init<<<9, 256>>>();

    // Weight splits + embedding gather
    k_split_sani<<<2048, 256>>>(W_sani);
    k_split_in<<<1024, 256>>>(W_in);
    k_split_out<<<1024, 256>>>(W_out);
    k_gather<<<8192, 256>>>(labels, emb_table);

    // All GEMM work: one persistent dependency-driven kernel
    k_sani<<<NCTA, 256>>>(b_in, b_sani, b_out);

    // Loss
    k_loss<<<NB, 512>>>(labels, emb_table);
    k_final<<<1, 128>>>((float*)d_out);
}

// round 11
// speedup vs baseline: 2.3800x; 1.0386x over previous
#include <cuda_runtime.h>
#include <cuda_bf16.h>
#include <cstdint>

// ---------------------------------------------------------------------------
// Problem constants
// ---------------------------------------------------------------------------
#define NB   128
#define LL   64
#define HH   512
#define EE   512
#define NCELL 2080
#define CELLF 65536   // 128*512

typedef __nv_bfloat16 bf16;

// Tile config: each task = 64(M) x 64(N), K full. 16 tasks per logical cell
// (2 M-halves x 8 N-slices). 8 warps: 2(m) x 4(n), warp tile 32x16.
#define RSB    80                 // smem row stride bytes (64 data + 16 pad)
#define TILE_B (64 * RSB)         // 5120 bytes per operand tile
#define STAGE_B (4 * TILE_B)      // Ahi, Alo, Whi, Wlo = 20480
// total static smem = 2 * STAGE_B = 40960 (2 CTAs/SM -> 80KB/SM)

#define NLCELL 2144               // 64 input + 2016 wave + 64 output
#define NTASK  (NLCELL * 16)
#define NCTA   296                // 2 per SM

// ---------------------------------------------------------------------------
// Device scratch (allocation-free)
// ---------------------------------------------------------------------------
__device__ bf16 g_Hhi[(size_t)NCELL * CELLF];
__device__ bf16 g_Hlo[(size_t)NCELL * CELLF];
__device__ bf16 g_Whi[HH * 2 * HH], g_Wlo[HH * 2 * HH];
__device__ bf16 g_WinHi[HH * EE],  g_WinLo[HH * EE];
__device__ bf16 g_WoutHi[EE * HH], g_WoutLo[EE * HH];
__device__ bf16 g_Xhi[8192 * EE],  g_Xlo[8192 * EE];
__device__ float g_y[8192 * 512];
__device__ float g_part[NB];

// Scheduling state
__device__ int  g_next;
__device__ int  g_doneH[NCELL * 2];   // completed tiles per (cell, m-half); 8 = ready
__device__ int2 g_list[NLCELL];       // ordered logical cells: (s, k); k==0 input, k>0 wave, k==-1 output

__device__ __forceinline__ int cellidx(int s, int k) { return s * (s + 1) / 2 + k; }

__device__ __forceinline__ uint32_t smem_u32(const void* p) {
    uint32_t a;
    asm("{ .reg .u64 t; cvta.to.shared.u64 t, %1; cvt.u32.u64 %0, t; }" : "=r"(a) : "l"(p));
    return a;
}
__device__ __forceinline__ void cpa16(uint32_t dst, const void* src) {
    asm volatile("cp.async.ca.shared.global [%0], [%1], 16;" :: "r"(dst), "l"(src));
}
__device__ __forceinline__ void cp_commit() { asm volatile("cp.async.commit_group;" ::: "memory"); }
__device__ __forceinline__ void cp_wait1()  { asm volatile("cp.async.wait_group 1;" ::: "memory"); }
__device__ __forceinline__ void cp_wait0()  { asm volatile("cp.async.wait_group 0;" ::: "memory"); }

__device__ __forceinline__ int ld_acq(const int* p) {
    int v;
    asm volatile("ld.acquire.gpu.global.b32 %0, [%1];" : "=r"(v) : "l"(p));
    return v;
}
__device__ __forceinline__ void red_rel(int* p) {
    asm volatile("red.release.gpu.global.add.s32 [%0], 1;" :: "l"(p));
}

__device__ __forceinline__ void mma16816(float c[4], const uint32_t a[4], uint32_t b0, uint32_t b1) {
    asm volatile(
        "mma.sync.aligned.m16n8k16.row.col.f32.bf16.bf16.f32 "
        "{%0,%1,%2,%3},{%4,%5,%6,%7},{%8,%9},{%0,%1,%2,%3};"
        : "+f"(c[0]), "+f"(c[1]), "+f"(c[2]), "+f"(c[3])
        : "r"(a[0]), "r"(a[1]), "r"(a[2]), "r"(a[3]), "r"(b0), "r"(b1));
}

// ---------------------------------------------------------------------------
// Init: zero flags, reset counter, build interleaved topological cell list
// ---------------------------------------------------------------------------
__global__ void k_init()
{
    int i = blockIdx.x * blockDim.x + threadIdx.x;
    if (i < NCELL * 2) g_doneH[i] = 0;
    if (i == 0) g_next = 0;
    if (i == 1) {
        int idx = 0;
        for (int s = 0; s < 64; ++s) g_list[idx++] = make_int2(s, 0);   // inputs
        g_list[idx++] = make_int2(0, -1);                               // output 0 (dep: input cell 0)
        for (int d = 2; d <= 126; ++d) {
            int s_lo = (d + 1) / 2;
            if (d - 63 > s_lo) s_lo = d - 63;
            int s_hi = (d - 1 < 63) ? d - 1 : 63;
            for (int s = s_lo; s <= s_hi; ++s)
                g_list[idx++] = make_int2(s, d - s);                    // wave cells
            if ((d & 1) == 0)
                g_list[idx++] = make_int2(d / 2, -1);                   // output s=d/2 (dep: (s,s) on diag d)
        }
    }
}

// ---------------------------------------------------------------------------
// Persistent SANI kernel: dependency-driven task loop over all GEMM tiles.
// Task t: lcell = t>>4, tile = t&15 -> mh = tile&1 (M-half), ns = tile>>1.
// ---------------------------------------------------------------------------
__global__ void __launch_bounds__(256, 2)
k_sani(const float* __restrict__ b_in, const float* __restrict__ b_sani,
       const float* __restrict__ b_out)
{
    __shared__ __align__(128) char smem[2 * STAGE_B];
    __shared__ int sh_task;

    const uint32_t sbase = smem_u32(smem);
    const int tid = threadIdx.x;
    const int wid = tid >> 5, lane = tid & 31;
    const int wm = wid & 1, wn = wid >> 1;       // warp grid 2(m) x 4(n)
    const int lr = lane >> 2;                    // 0..7
    const int lc2 = (lane & 3) * 2;              // 0,2,4,6

    for (;;) {
        if (tid == 0) sh_task = atomicAdd(&g_next, 1);
        __syncthreads();
        const int t = sh_task;
        __syncthreads();          // protect sh_task before next iteration's write
        if (t >= NTASK) return;

        const int lcell = t >> 4;
        const int tile  = t & 15;
        const int mh = tile & 1;                 // M-half (64 rows)
        const int n0 = (tile >> 1) * 64;         // N-slice base (0..448)

        const int2 cc = g_list[lcell];
        const int s = cc.x, k = cc.y;
        const int type = (k < 0) ? 2 : (k == 0 ? 0 : 1);

        // ---- dependency wait (thread 0 polls half-cell counters) ----
        if (tid == 0) {
            if (type == 1) {
                const int* p1 = &g_doneH[cellidx(s - 1, k - 1) * 2 + mh];
                const int* p2 = &g_doneH[cellidx(s,     k - 1) * 2 + mh];
                while (ld_acq(p1) < 8) __nanosleep(64);
                while (ld_acq(p2) < 8) __nanosleep(64);
            } else if (type == 2) {
                const int* p = &g_doneH[cellidx(s, s) * 2 + mh];
                while (ld_acq(p) < 8) __nanosleep(64);
            }
        }
        __syncthreads();

        // ---- operand pointers ----
        const bf16 *aH1, *aL1, *aH2 = nullptr, *aL2 = nullptr, *wH, *wL;
        const float* bias;
        int ldw, nch;
        size_t rowbase = (size_t)mh * 64 * 512;
        if (type == 0) {
            size_t xb = (size_t)s * 128 * 512 + rowbase;
            aH1 = g_Xhi + xb;  aL1 = g_Xlo + xb;
            wH = g_WinHi + (size_t)n0 * 512;  wL = g_WinLo + (size_t)n0 * 512;
            ldw = 512; nch = 16; bias = b_in;
        } else if (type == 1) {
            size_t pa = (size_t)cellidx(s - 1, k - 1) * CELLF + rowbase;
            size_t pb = (size_t)cellidx(s,     k - 1) * CELLF + rowbase;
            aH1 = g_Hhi + pa;  aL1 = g_Hlo + pa;
            aH2 = g_Hhi + pb;  aL2 = g_Hlo + pb;
            wH = g_Whi + (size_t)n0 * 1024;  wL = g_Wlo + (size_t)n0 * 1024;
            ldw = 1024; nch = 32; bias = b_sani;
        } else {
            size_t pa = (size_t)cellidx(s, s) * CELLF + rowbase;
            aH1 = g_Hhi + pa;  aL1 = g_Hlo + pa;
            wH = g_WoutHi + (size_t)n0 * 512;  wL = g_WoutLo + (size_t)n0 * 512;
            ldw = 512; nch = 16; bias = b_out;
        }

        // ---- GEMM: 64x64, K = nch*32, 3-product bf16 split ----
        float acc[2][2][4];
        #pragma unroll
        for (int i = 0; i < 2; ++i)
            #pragma unroll
            for (int j = 0; j < 2; ++j)
                #pragma unroll
                for (int q = 0; q < 4; ++q) acc[i][j][q] = 0.f;

        auto issue = [&](int c) {
            const bf16* ah; const bf16* al; int ka;
            if (c < 16) { ah = aH1; al = aL1; ka = c * 32; }
            else        { ah = aH2; al = aL2; ka = (c - 16) * 32; }
            const int kw = c * 32;
            const uint32_t sm = sbase + (uint32_t)(c & 1) * STAGE_B;
            const int row = tid >> 2, seg = tid & 3;
            const uint32_t off = (uint32_t)(row * RSB + seg * 16);
            cpa16(sm + 0 * TILE_B + off, ah + (size_t)row * 512 + ka + seg * 8);
            cpa16(sm + 1 * TILE_B + off, al + (size_t)row * 512 + ka + seg * 8);
            cpa16(sm + 2 * TILE_B + off, wH + (size_t)row * ldw + kw + seg * 8);
            cpa16(sm + 3 * TILE_B + off, wL + (size_t)row * ldw + kw + seg * 8);
            cp_commit();
        };

        issue(0);
        issue(1);

        for (int c = 0; c < nch; ++c) {
            if (c + 1 < nch) cp_wait1(); else cp_wait0();
            __syncthreads();

            const char* st = smem + (size_t)(c & 1) * STAGE_B;
            #pragma unroll
            for (int ks = 0; ks < 2; ++ks) {
                const int k0 = ks * 16;
                // Preload all fragments, then issue MMAs product-major so
                // same-accumulator reuses are 4 MMAs apart (no RAW chains).
                uint32_t bh[2][2], bl[2][2];
                #pragma unroll
                for (int ni = 0; ni < 2; ++ni) {
                    const int nrow = wn * 16 + ni * 8 + lr;
                    const char* ph = st + 2 * TILE_B + nrow * RSB + (k0 + lc2) * 2;
                    bh[ni][0] = *(const uint32_t*)ph;
                    bh[ni][1] = *(const uint32_t*)(ph + 16);
                    const char* pl = st + 3 * TILE_B + nrow * RSB + (k0 + lc2) * 2;
                    bl[ni][0] = *(const uint32_t*)pl;
                    bl[ni][1] = *(const uint32_t*)(pl + 16);
                }
                uint32_t ah[2][4], alr[2][4];
                #pragma unroll
                for (int mi = 0; mi < 2; ++mi) {
                    const int mrow = wm * 32 + mi * 16 + lr;
                    const char* ph = st + 0 * TILE_B + mrow * RSB + (k0 + lc2) * 2;
                    ah[mi][0] = *(const uint32_t*)ph;
                    ah[mi][1] = *(const uint32_t*)(ph + 8 * RSB);
                    ah[mi][2] = *(const uint32_t*)(ph + 16);
                    ah[mi][3] = *(const uint32_t*)(ph + 8 * RSB + 16);
                    const char* pl = st + 1 * TILE_B + mrow * RSB + (k0 + lc2) * 2;
                    alr[mi][0] = *(const uint32_t*)pl;
                    alr[mi][1] = *(const uint32_t*)(pl + 8 * RSB);
                    alr[mi][2] = *(const uint32_t*)(pl + 16);
                    alr[mi][3] = *(const uint32_t*)(pl + 8 * RSB + 16);
                }
                #pragma unroll
                for (int mi = 0; mi < 2; ++mi)
                    #pragma unroll
                    for (int ni = 0; ni < 2; ++ni)
                        mma16816(acc[mi][ni], ah[mi], bh[ni][0], bh[ni][1]);
                #pragma unroll
                for (int mi = 0; mi < 2; ++mi)
                    #pragma unroll
                    for (int ni = 0; ni < 2; ++ni)
                        mma16816(acc[mi][ni], ah[mi], bl[ni][0], bl[ni][1]);
                #pragma unroll
                for (int mi = 0; mi < 2; ++mi)
                    #pragma unroll
                    for (int ni = 0; ni < 2; ++ni)
                        mma16816(acc[mi][ni], alr[mi], bh[ni][0], bh[ni][1]);
            }
            __syncthreads();
            if (c + 2 < nch) issue(c + 2);
        }

        // ---- epilogue ----
        int dstCell = (type == 0) ? cellidx(s, 0) : (type == 1 ? cellidx(s, k) : -1);
        bf16* outHi = (dstCell >= 0) ? g_Hhi + (size_t)dstCell * CELLF : nullptr;
        bf16* outLo = (dstCell >= 0) ? g_Hlo + (size_t)dstCell * CELLF : nullptr;
        float* outF = (type == 2) ? g_y + (size_t)s * 128 * 512 : nullptr;

        #pragma unroll
        for (int mi = 0; mi < 2; ++mi) {
            const int r0 = mh * 64 + wm * 32 + mi * 16 + lr;   // row within 128
            #pragma unroll
            for (int ni = 0; ni < 2; ++ni) {
                const int ccol = n0 + wn * 16 + ni * 8 + lc2;
                const float bx = bias[ccol];
                const float by = bias[ccol + 1];
                #pragma unroll
                for (int half = 0; half < 2; ++half) {
                    const int r = r0 + half * 8;
                    const float v0 = acc[mi][ni][half * 2]     + bx;
                    const float v1 = acc[mi][ni][half * 2 + 1] + by;
                    if (outF) {
                        float2 fv; fv.x = v0; fv.y = v1;
                        *reinterpret_cast<float2*>(outF + (size_t)r * 512 + ccol) = fv;
                    } else {
                        bf16 h0 = __float2bfloat16(v0), h1 = __float2bfloat16(v1);
                        bf16 e0 = __float2bfloat16(v0 - __bfloat162float(h0));
                        bf16 e1 = __float2bfloat16(v1 - __bfloat162float(h1));
                        __nv_bfloat162 hp; hp.x = h0; hp.y = h1;
                        __nv_bfloat162 lp; lp.x = e0; lp.y = e1;
                        *reinterpret_cast<__nv_bfloat162*>(outHi + (size_t)r * 512 + ccol) = hp;
                        *reinterpret_cast<__nv_bfloat162*>(outLo + (size_t)r * 512 + ccol) = lp;
                    }
                }
            }
        }

        // ---- signal completion (per cell half) ----
        if (dstCell >= 0) {
            __threadfence();
            __syncthreads();
            if (tid == 0) red_rel(&g_doneH[dstCell * 2 + mh]);
        }
    }
}

// ---------------------------------------------------------------------------
// Prep kernels
// ---------------------------------------------------------------------------
__global__ void k_split_sani(const float* __restrict__ src) {
    int i = blockIdx.x * blockDim.x + threadIdx.x;
    float v = src[i];
    bf16 h = __float2bfloat16(v);
    g_Whi[i] = h;
    g_Wlo[i] = __float2bfloat16(v - __bfloat162float(h));
}
__global__ void k_split_in(const float* __restrict__ src) {
    int i = blockIdx.x * blockDim.x + threadIdx.x;
    float v = src[i];
    bf16 h = __float2bfloat16(v);
    g_WinHi[i] = h;
    g_WinLo[i] = __float2bfloat16(v - __bfloat162float(h));
}
__global__ void k_split_out(const float* __restrict__ src) {
    int i = blockIdx.x * blockDim.x + threadIdx.x;
    float v = src[i];
    bf16 h = __float2bfloat16(v);
    g_WoutHi[i] = h;
    g_WoutLo[i] = __float2bfloat16(v - __bfloat162float(h));
}

__global__ void __launch_bounds__(256)
k_gather(const int* __restrict__ labels, const float* __restrict__ emb)
{
    const int r = blockIdx.x;            // r = s*128 + n
    const int n = r & 127, s = r >> 7;
    const float* row = emb + (size_t)labels[n * LL + s] * EE;
    const int e = threadIdx.x * 2;
    float2 v = *reinterpret_cast<const float2*>(row + e);
    bf16 h0 = __float2bfloat16(v.x), h1 = __float2bfloat16(v.y);
    bf16 l0 = __float2bfloat16(v.x - __bfloat162float(h0));
    bf16 l1 = __float2bfloat16(v.y - __bfloat162float(h1));
    __nv_bfloat162 hp; hp.x = h0; hp.y = h1;
    __nv_bfloat162 lp; lp.x = l0; lp.y = l1;
    *reinterpret_cast<__nv_bfloat162*>(g_Xhi + (size_t)r * EE + e) = hp;
    *reinterpret_cast<__nv_bfloat162*>(g_Xlo + (size_t)r * EE + e) = lp;
}

// ---------------------------------------------------------------------------
// Loss (flat row r = s*128+n; reshape(N,L,E) reads flat row n*64+l)
// ---------------------------------------------------------------------------
__global__ void __launch_bounds__(512)
k_loss(const int* __restrict__ labels, const float* __restrict__ emb_table)
{
    __shared__ float red[512];
    const int n = blockIdx.x;
    const int e = threadIdx.x;
    const float* yb = g_y + (size_t)n * LL * EE + e;

    float m = -1e30f;
    #pragma unroll
    for (int l = 0; l < LL; ++l) m = fmaxf(m, yb[(size_t)l * EE]);

    float se = 0.f, dot = 0.f, sume = 0.f;
    #pragma unroll
    for (int l = 0; l < LL; ++l) {
        float yv = yb[(size_t)l * EE];
        float ev = emb_table[(size_t)labels[n * LL + l] * EE + e];
        se   += expf(yv - m);
        dot  += ev * yv;
        sume += ev;
    }
    float lse = m + logf(se);
    red[e] = dot - sume * lse;
    __syncthreads();
    for (int stride = 256; stride > 0; stride >>= 1) {
        if (e < stride) red[e] += red[e + stride];
        __syncthreads();
    }
    if (e == 0) g_part[n] = red[0];
}

__global__ void k_final(float* __restrict__ out)
{
    __shared__ float red[128];
    const int t = threadIdx.x;
    red[t] = g_part[t];
    __syncthreads();
    for (int stride = 64; stride > 0; stride >>= 1) {
        if (t < stride) red[t] += red[t + stride];
        __syncthreads();
    }
    if (t == 0) out[0] = -red[0] / (float)(NB * EE);
}

// ---------------------------------------------------------------------------
extern "C" void kernel_launch(void* const* d_in, const int* in_sizes, int n_in,
                              void* d_out, int out_size)
{
    const int*   labels    = (const int*)  d_in[0];
    const float* emb_table = (const float*)d_in[1];
    const float* W_in      = (const float*)d_in[2];
    const float* b_in      = (const float*)d_in[3];
    const float* W_sani    = (const float*)d_in[4];
    const float* b_sani    = (const float*)d_in[5];
    const float* W_out     = (const float*)d_in[6];
    const float* b_out     = (const float*)d_in[7];

    // Scheduling state reset + task list build
    k_init<<<17, 256>>>();

    // Weight splits + embedding gather
    k_split_sani<<<2048, 256>>>(W_sani);
    k_split_in<<<1024, 256>>>(W_in);
    k_split_out<<<1024, 256>>>(W_out);
    k_gather<<<8192, 256>>>(labels, emb_table);

    // All GEMM work: one persistent dependency-driven kernel (2 CTAs/SM)
    k_sani<<<NCTA, 256>>>(b_in, b_sani, b_out);

    // Loss
    k_loss<<<NB, 512>>>(labels, emb_table);
    k_final<<<1, 128>>>((float*)d_out);
}

// round 12
// speedup vs baseline: 2.8338x; 1.1907x over previous
#include <cuda_runtime.h>
#include <cuda_bf16.h>
#include <cstdint>

// ---------------------------------------------------------------------------
// Problem constants
// ---------------------------------------------------------------------------
#define NB   128
#define LL   64
#define HH   512
#define EE   512
#define NCELL 2080
#define CELLF 65536   // 128*512

typedef __nv_bfloat16 bf16;

// Tile config: task = 64(M) x 64(N), K full. 16 tasks per logical cell.
// 8 warps: 2(m) x 4(n), warp tile 32x16.
#define RSB    80                 // smem row stride bytes (64 data + 16 pad)
#define TILE_B (64 * RSB)         // 5120 bytes per operand tile
#define STAGE_B (4 * TILE_B)      // Ahi, Alo, Whi, Wlo = 20480
#define NSTAGE 4
#define GSMEM (NSTAGE * STAGE_B)  // 81920 dynamic

#define NLCELL 2144               // 64 input + 2016 wave + 64 output
#define NTASK  (NLCELL * 16)
#define NCTA   296                // 2 per SM

// ---------------------------------------------------------------------------
// Device scratch (allocation-free)
// ---------------------------------------------------------------------------
__device__ bf16 g_Hhi[(size_t)NCELL * CELLF];
__device__ bf16 g_Hlo[(size_t)NCELL * CELLF];
__device__ bf16 g_Whi[HH * 2 * HH], g_Wlo[HH * 2 * HH];
__device__ bf16 g_WinHi[HH * EE],  g_WinLo[HH * EE];
__device__ bf16 g_WoutHi[EE * HH], g_WoutLo[EE * HH];
__device__ bf16 g_Xhi[8192 * EE],  g_Xlo[8192 * EE];
__device__ float g_y[8192 * 512];
__device__ float g_part[NB];

// Scheduling state
__device__ int  g_next;
__device__ int  g_doneH[NCELL * 2];   // completed tiles per (cell, m-half); 8 = ready
__device__ int2 g_list[NLCELL];       // (s, k); k==0 input, k>0 wave, k==-1 output

__device__ __forceinline__ int cellidx(int s, int k) { return s * (s + 1) / 2 + k; }

__device__ __forceinline__ uint32_t smem_u32(const void* p) {
    uint32_t a;
    asm("{ .reg .u64 t; cvta.to.shared.u64 t, %1; cvt.u32.u64 %0, t; }" : "=r"(a) : "l"(p));
    return a;
}
__device__ __forceinline__ void cpa16(uint32_t dst, const void* src) {
    asm volatile("cp.async.ca.shared.global [%0], [%1], 16;" :: "r"(dst), "l"(src));
}
__device__ __forceinline__ void cp_commit() { asm volatile("cp.async.commit_group;" ::: "memory"); }
__device__ __forceinline__ void cp_wait2()  { asm volatile("cp.async.wait_group 2;" ::: "memory"); }

__device__ __forceinline__ int ld_acq(const int* p) {
    int v;
    asm volatile("ld.acquire.gpu.global.b32 %0, [%1];" : "=r"(v) : "l"(p));
    return v;
}
__device__ __forceinline__ void red_rel(int* p) {
    asm volatile("red.release.gpu.global.add.s32 [%0], 1;" :: "l"(p));
}

#define LDM4(r0, r1, r2, r3, addr) \
    asm volatile("ldmatrix.sync.aligned.m8n8.x4.shared.b16 {%0,%1,%2,%3}, [%4];" \
                 : "=r"(r0), "=r"(r1), "=r"(r2), "=r"(r3) : "r"(addr))

__device__ __forceinline__ void mma16816(float c[4], const uint32_t a[4], uint32_t b0, uint32_t b1) {
    asm volatile(
        "mma.sync.aligned.m16n8k16.row.col.f32.bf16.bf16.f32 "
        "{%0,%1,%2,%3},{%4,%5,%6,%7},{%8,%9},{%0,%1,%2,%3};"
        : "+f"(c[0]), "+f"(c[1]), "+f"(c[2]), "+f"(c[3])
        : "r"(a[0]), "r"(a[1]), "r"(a[2]), "r"(a[3]), "r"(b0), "r"(b1));
}

// ---------------------------------------------------------------------------
// Init: zero flags, reset counter, build interleaved topological cell list
// ---------------------------------------------------------------------------
__global__ void k_init()
{
    int i = blockIdx.x * blockDim.x + threadIdx.x;
    if (i < NCELL * 2) g_doneH[i] = 0;
    if (i == 0) g_next = 0;
    if (i == 1) {
        int idx = 0;
        for (int s = 0; s < 64; ++s) g_list[idx++] = make_int2(s, 0);   // inputs
        g_list[idx++] = make_int2(0, -1);                               // output 0
        for (int d = 2; d <= 126; ++d) {
            int s_lo = (d + 1) / 2;
            if (d - 63 > s_lo) s_lo = d - 63;
            int s_hi = (d - 1 < 63) ? d - 1 : 63;
            for (int s = s_lo; s <= s_hi; ++s)
                g_list[idx++] = make_int2(s, d - s);                    // wave cells
            if ((d & 1) == 0)
                g_list[idx++] = make_int2(d / 2, -1);                   // output s=d/2
        }
    }
}

// ---------------------------------------------------------------------------
// Persistent SANI kernel: dependency-driven task loop over all GEMM tiles.
// ---------------------------------------------------------------------------
__global__ void __launch_bounds__(256, 2)
k_sani(const float* __restrict__ b_in, const float* __restrict__ b_sani,
       const float* __restrict__ b_out)
{
    extern __shared__ __align__(128) char smem[];
    __shared__ int sh_task;

    const uint32_t sbase = smem_u32(smem);
    const int tid = threadIdx.x;
    const int wid = tid >> 5, lane = tid & 31;
    const int wm = wid & 1, wn = wid >> 1;       // warp grid 2(m) x 4(n)
    const int lr = lane >> 2;                    // 0..7
    const int lc2 = (lane & 3) * 2;              // 0,2,4,6

    // ldmatrix per-lane address components (byte offsets within a stage)
    const int arow = (lane & 7) + ((lane & 8) ? 8 : 0);
    const int akb  = ((lane & 16) ? 8 : 0) * 2;
    const uint32_t aHiOff0 = (uint32_t)(0 * TILE_B + (wm * 32 + 0 * 16 + arow) * RSB) + akb;
    const uint32_t aHiOff1 = (uint32_t)(0 * TILE_B + (wm * 32 + 1 * 16 + arow) * RSB) + akb;
    const uint32_t aLoOff0 = aHiOff0 + TILE_B;
    const uint32_t aLoOff1 = aHiOff1 + TILE_B;
    const int bnrow = wn * 16 + ((lane >> 4) & 1) * 8 + (lane & 7);
    const int bkb   = ((lane >> 3) & 1) * 8 * 2;
    const uint32_t bHiOff = (uint32_t)(2 * TILE_B + bnrow * RSB) + bkb;
    const uint32_t bLoOff = bHiOff + TILE_B;

    for (;;) {
        if (tid == 0) sh_task = atomicAdd(&g_next, 1);
        __syncthreads();
        const int t = sh_task;
        __syncthreads();          // protect sh_task before next iteration's write
        if (t >= NTASK) return;

        const int lcell = t >> 4;
        const int tile  = t & 15;
        const int mh = tile & 1;                 // M-half (64 rows)
        const int n0 = (tile >> 1) * 64;         // N-slice base (0..448)

        const int2 cc = g_list[lcell];
        const int s = cc.x, k = cc.y;
        const int type = (k < 0) ? 2 : (k == 0 ? 0 : 1);

        // ---- dependency wait ----
        if (tid == 0) {
            if (type == 1) {
                const int* p1 = &g_doneH[cellidx(s - 1, k - 1) * 2 + mh];
                const int* p2 = &g_doneH[cellidx(s,     k - 1) * 2 + mh];
                while (ld_acq(p1) < 8) __nanosleep(64);
                while (ld_acq(p2) < 8) __nanosleep(64);
            } else if (type == 2) {
                const int* p = &g_doneH[cellidx(s, s) * 2 + mh];
                while (ld_acq(p) < 8) __nanosleep(64);
            }
        }
        __syncthreads();

        // ---- operand pointers ----
        const bf16 *aH1, *aL1, *aH2 = nullptr, *aL2 = nullptr, *wH, *wL;
        const float* bias;
        int ldw, nch;
        size_t rowbase = (size_t)mh * 64 * 512;
        if (type == 0) {
            size_t xb = (size_t)s * 128 * 512 + rowbase;
            aH1 = g_Xhi + xb;  aL1 = g_Xlo + xb;
            wH = g_WinHi + (size_t)n0 * 512;  wL = g_WinLo + (size_t)n0 * 512;
            ldw = 512; nch = 16; bias = b_in;
        } else if (type == 1) {
            size_t pa = (size_t)cellidx(s - 1, k - 1) * CELLF + rowbase;
            size_t pb = (size_t)cellidx(s,     k - 1) * CELLF + rowbase;
            aH1 = g_Hhi + pa;  aL1 = g_Hlo + pa;
            aH2 = g_Hhi + pb;  aL2 = g_Hlo + pb;
            wH = g_Whi + (size_t)n0 * 1024;  wL = g_Wlo + (size_t)n0 * 1024;
            ldw = 1024; nch = 32; bias = b_sani;
        } else {
            size_t pa = (size_t)cellidx(s, s) * CELLF + rowbase;
            aH1 = g_Hhi + pa;  aL1 = g_Hlo + pa;
            wH = g_WoutHi + (size_t)n0 * 512;  wL = g_WoutLo + (size_t)n0 * 512;
            ldw = 512; nch = 16; bias = b_out;
        }

        // ---- GEMM: 64x64, K = nch*32, 3-product bf16 split ----
        float acc[2][2][4];
        #pragma unroll
        for (int i = 0; i < 2; ++i)
            #pragma unroll
            for (int j = 0; j < 2; ++j)
                #pragma unroll
                for (int q = 0; q < 4; ++q) acc[i][j][q] = 0.f;

        auto issue = [&](int c) {
            const bf16* ah; const bf16* al; int ka;
            if (c < 16) { ah = aH1; al = aL1; ka = c * 32; }
            else        { ah = aH2; al = aL2; ka = (c - 16) * 32; }
            const int kw = c * 32;
            const uint32_t sm = sbase + (uint32_t)(c & (NSTAGE - 1)) * STAGE_B;
            const int row = tid >> 2, seg = tid & 3;
            const uint32_t off = (uint32_t)(row * RSB + seg * 16);
            cpa16(sm + 0 * TILE_B + off, ah + (size_t)row * 512 + ka + seg * 8);
            cpa16(sm + 1 * TILE_B + off, al + (size_t)row * 512 + ka + seg * 8);
            cpa16(sm + 2 * TILE_B + off, wH + (size_t)row * ldw + kw + seg * 8);
            cpa16(sm + 3 * TILE_B + off, wL + (size_t)row * ldw + kw + seg * 8);
            cp_commit();
        };

        issue(0); issue(1); issue(2);

        for (int c = 0; c < nch; ++c) {
            cp_wait2();           // 3 groups outstanding -> group c complete
            __syncthreads();      // one barrier per chunk (issue happens after
                                  // this sync, targeting stage c-1's buffer)

            const uint32_t stg = sbase + (uint32_t)(c & (NSTAGE - 1)) * STAGE_B;
            #pragma unroll
            for (int ks = 0; ks < 2; ++ks) {
                const uint32_t kb = stg + ks * 32;   // k0*2 bytes
                uint32_t ah[2][4], al[2][4], bh[4], bl[4];
                LDM4(ah[0][0], ah[0][1], ah[0][2], ah[0][3], kb + aHiOff0);
                LDM4(ah[1][0], ah[1][1], ah[1][2], ah[1][3], kb + aHiOff1);
                LDM4(al[0][0], al[0][1], al[0][2], al[0][3], kb + aLoOff0);
                LDM4(al[1][0], al[1][1], al[1][2], al[1][3], kb + aLoOff1);
                LDM4(bh[0], bh[1], bh[2], bh[3], kb + bHiOff);
                LDM4(bl[0], bl[1], bl[2], bl[3], kb + bLoOff);
                // product-major: 4 independent accumulators between reuses
                #pragma unroll
                for (int mi = 0; mi < 2; ++mi)
                    #pragma unroll
                    for (int ni = 0; ni < 2; ++ni)
                        mma16816(acc[mi][ni], ah[mi], bh[ni * 2], bh[ni * 2 + 1]);
                #pragma unroll
                for (int mi = 0; mi < 2; ++mi)
                    #pragma unroll
                    for (int ni = 0; ni < 2; ++ni)
                        mma16816(acc[mi][ni], ah[mi], bl[ni * 2], bl[ni * 2 + 1]);
                #pragma unroll
                for (int mi = 0; mi < 2; ++mi)
                    #pragma unroll
                    for (int ni = 0; ni < 2; ++ni)
                        mma16816(acc[mi][ni], al[mi], bh[ni * 2], bh[ni * 2 + 1]);
            }
            if (c + 3 < nch) issue(c + 3);
            else cp_commit();     // empty group keeps wait-depth uniform
        }

        // ---- epilogue ----
        int dstCell = (type == 0) ? cellidx(s, 0) : (type == 1 ? cellidx(s, k) : -1);
        bf16* outHi = (dstCell >= 0) ? g_Hhi + (size_t)dstCell * CELLF : nullptr;
        bf16* outLo = (dstCell >= 0) ? g_Hlo + (size_t)dstCell * CELLF : nullptr;
        float* outF = (type == 2) ? g_y + (size_t)s * 128 * 512 : nullptr;

        #pragma unroll
        for (int mi = 0; mi < 2; ++mi) {
            const int r0 = mh * 64 + wm * 32 + mi * 16 + lr;   // row within 128
            #pragma unroll
            for (int ni = 0; ni < 2; ++ni) {
                const int ccol = n0 + wn * 16 + ni * 8 + lc2;
                const float bx = bias[ccol];
                const float by = bias[ccol + 1];
                #pragma unroll
                for (int half = 0; half < 2; ++half) {
                    const int r = r0 + half * 8;
                    const float v0 = acc[mi][ni][half * 2]     + bx;
                    const float v1 = acc[mi][ni][half * 2 + 1] + by;
                    if (outF) {
                        float2 fv; fv.x = v0; fv.y = v1;
                        *reinterpret_cast<float2*>(outF + (size_t)r * 512 + ccol) = fv;
                    } else {
                        bf16 h0 = __float2bfloat16(v0), h1 = __float2bfloat16(v1);
                        bf16 e0 = __float2bfloat16(v0 - __bfloat162float(h0));
                        bf16 e1 = __float2bfloat16(v1 - __bfloat162float(h1));
                        __nv_bfloat162 hp; hp.x = h0; hp.y = h1;
                        __nv_bfloat162 lp; lp.x = e0; lp.y = e1;
                        *reinterpret_cast<__nv_bfloat162*>(outHi + (size_t)r * 512 + ccol) = hp;
                        *reinterpret_cast<__nv_bfloat162*>(outLo + (size_t)r * 512 + ccol) = lp;
                    }
                }
            }
        }

        // ---- signal completion (per cell half) ----
        if (dstCell >= 0) {
            __threadfence();
            __syncthreads();
            if (tid == 0) red_rel(&g_doneH[dstCell * 2 + mh]);
        }
    }
}

// ---------------------------------------------------------------------------
// Prep kernels
// ---------------------------------------------------------------------------
__global__ void k_split_sani(const float* __restrict__ src) {
    int i = blockIdx.x * blockDim.x + threadIdx.x;
    float v = src[i];
    bf16 h = __float2bfloat16(v);
    g_Whi[i] = h;
    g_Wlo[i] = __float2bfloat16(v - __bfloat162float(h));
}
__global__ void k_split_in(const float* __restrict__ src) {
    int i = blockIdx.x * blockDim.x + threadIdx.x;
    float v = src[i];
    bf16 h = __float2bfloat16(v);
    g_WinHi[i] = h;
    g_WinLo[i] = __float2bfloat16(v - __bfloat162float(h));
}
__global__ void k_split_out(const float* __restrict__ src) {
    int i = blockIdx.x * blockDim.x + threadIdx.x;
    float v = src[i];
    bf16 h = __float2bfloat16(v);
    g_WoutHi[i] = h;
    g_WoutLo[i] = __float2bfloat16(v - __bfloat162float(h));
}

__global__ void __launch_bounds__(256)
k_gather(const int* __restrict__ labels, const float* __restrict__ emb)
{
    const int r = blockIdx.x;            // r = s*128 + n
    const int n = r & 127, s = r >> 7;
    const float* row = emb + (size_t)labels[n * LL + s] * EE;
    const int e = threadIdx.x * 2;
    float2 v = *reinterpret_cast<const float2*>(row + e);
    bf16 h0 = __float2bfloat16(v.x), h1 = __float2bfloat16(v.y);
    bf16 l0 = __float2bfloat16(v.x - __bfloat162float(h0));
    bf16 l1 = __float2bfloat16(v.y - __bfloat162float(h1));
    __nv_bfloat162 hp; hp.x = h0; hp.y = h1;
    __nv_bfloat162 lp; lp.x = l0; lp.y = l1;
    *reinterpret_cast<__nv_bfloat162*>(g_Xhi + (size_t)r * EE + e) = hp;
    *reinterpret_cast<__nv_bfloat162*>(g_Xlo + (size_t)r * EE + e) = lp;
}

// ---------------------------------------------------------------------------
// Loss (flat row r = s*128+n; reshape(N,L,E) reads flat row n*64+l)
// ---------------------------------------------------------------------------
__global__ void __launch_bounds__(512)
k_loss(const int* __restrict__ labels, const float* __restrict__ emb_table)
{
    __shared__ float red[512];
    const int n = blockIdx.x;
    const int e = threadIdx.x;
    const float* yb = g_y + (size_t)n * LL * EE + e;

    float m = -1e30f;
    #pragma unroll
    for (int l = 0; l < LL; ++l) m = fmaxf(m, yb[(size_t)l * EE]);

    float se = 0.f, dot = 0.f, sume = 0.f;
    #pragma unroll
    for (int l = 0; l < LL; ++l) {
        float yv = yb[(size_t)l * EE];
        float ev = emb_table[(size_t)labels[n * LL + l] * EE + e];
        se   += expf(yv - m);
        dot  += ev * yv;
        sume += ev;
    }
    float lse = m + logf(se);
    red[e] = dot - sume * lse;
    __syncthreads();
    for (int stride = 256; stride > 0; stride >>= 1) {
        if (e < stride) red[e] += red[e + stride];
        __syncthreads();
    }
    if (e == 0) g_part[n] = red[0];
}

__global__ void k_final(float* __restrict__ out)
{
    __shared__ float red[128];
    const int t = threadIdx.x;
    red[t] = g_part[t];
    __syncthreads();
    for (int stride = 64; stride > 0; stride >>= 1) {
        if (t < stride) red[t] += red[t + stride];
        __syncthreads();
    }
    if (t == 0) out[0] = -red[0] / (float)(NB * EE);
}

// ---------------------------------------------------------------------------
extern "C" void kernel_launch(void* const* d_in, const int* in_sizes, int n_in,
                              void* d_out, int out_size)
{
    const int*   labels    = (const int*)  d_in[0];
    const float* emb_table = (const float*)d_in[1];
    const float* W_in      = (const float*)d_in[2];
    const float* b_in      = (const float*)d_in[3];
    const float* W_sani    = (const float*)d_in[4];
    const float* b_sani    = (const float*)d_in[5];
    const float* W_out     = (const float*)d_in[6];
    const float* b_out     = (const float*)d_in[7];

    // Unconditional each call (no static guards; idempotent non-stream API)
    cudaFuncSetAttribute(k_sani, cudaFuncAttributeMaxDynamicSharedMemorySize, GSMEM);

    // Scheduling state reset + task list build
    k_init<<<17, 256>>>();

    // Weight splits + embedding gather
    k_split_sani<<<2048, 256>>>(W_sani);
    k_split_in<<<1024, 256>>>(W_in);
    k_split_out<<<1024, 256>>>(W_out);
    k_gather<<<8192, 256>>>(labels, emb_table);

    // All GEMM work: one persistent dependency-driven kernel (2 CTAs/SM)
    k_sani<<<NCTA, 256, GSMEM>>>(b_in, b_sani, b_out);

    // Loss
    k_loss<<<NB, 512>>>(labels, emb_table);
    k_final<<<1, 128>>>((float*)d_out);
}

// round 14
// speedup vs baseline: 3.1410x; 1.1084x over previous
#include <cuda_runtime.h>
#include <cuda_bf16.h>
#include <cstdint>

// ---------------------------------------------------------------------------
// Problem constants
// ---------------------------------------------------------------------------
#define NB   128
#define LL   64
#define HH   512
#define EE   512
#define NCELL 2080
#define CELLF 65536   // 128*512

typedef __nv_bfloat16 bf16;

// Tile config: task = 64(M) x 64(N), K full. 16 tasks per logical cell.
// 8 warps: 2(m) x 4(n), warp tile 32x16.
#define RSB    80                 // smem row stride bytes (64 data + 16 pad)
#define TILE_B (64 * RSB)         // 5120 bytes per operand tile
#define STAGE_B (4 * TILE_B)      // Ahi, Alo, Whi, Wlo = 20480
#define NSTAGE 4
#define GSMEM (NSTAGE * STAGE_B)  // 81920 dynamic

#define NLCELL 2144               // 64 input + 2016 wave + 64 output
#define NTASK  (NLCELL * 16)
#define NCTA   296                // 2 per SM

// B-source dependency wait chunk: loads for chunk 16 are prefetched at the
// end of chunk 13 (depth-3 lookahead), so the wait must complete by then.
#define BDEP_CHUNK 13

// ---------------------------------------------------------------------------
// Device scratch (allocation-free)
// ---------------------------------------------------------------------------
__device__ bf16 g_Hhi[(size_t)NCELL * CELLF];
__device__ bf16 g_Hlo[(size_t)NCELL * CELLF];
__device__ bf16 g_Whi[HH * 2 * HH], g_Wlo[HH * 2 * HH];
__device__ bf16 g_WinHi[HH * EE],  g_WinLo[HH * EE];
__device__ bf16 g_WoutHi[EE * HH], g_WoutLo[EE * HH];
__device__ bf16 g_Xhi[8192 * EE],  g_Xlo[8192 * EE];
__device__ float g_y[8192 * 512];
__device__ float g_part[NB];

// Scheduling state
__device__ int  g_next;
__device__ int  g_doneH[NCELL * 2];   // completed tiles per (cell, m-half); 8 = ready
__device__ int2 g_list[NLCELL];       // (s, k); k==0 input, k>0 wave, k==-1 output

__device__ __forceinline__ int cellidx(int s, int k) { return s * (s + 1) / 2 + k; }

__device__ __forceinline__ uint32_t smem_u32(const void* p) {
    uint32_t a;
    asm("{ .reg .u64 t; cvta.to.shared.u64 t, %1; cvt.u32.u64 %0, t; }" : "=r"(a) : "l"(p));
    return a;
}
__device__ __forceinline__ void cpa16(uint32_t dst, const void* src) {
    asm volatile("cp.async.ca.shared.global [%0], [%1], 16;" :: "r"(dst), "l"(src));
}
__device__ __forceinline__ void cp_commit() { asm volatile("cp.async.commit_group;" ::: "memory"); }
__device__ __forceinline__ void cp_wait2()  { asm volatile("cp.async.wait_group 2;" ::: "memory"); }

__device__ __forceinline__ int ld_acq(const int* p) {
    int v;
    asm volatile("ld.acquire.gpu.global.b32 %0, [%1];" : "=r"(v) : "l"(p));
    return v;
}
__device__ __forceinline__ void red_rel(int* p) {
    asm volatile("red.release.gpu.global.add.s32 [%0], 1;" :: "l"(p));
}

#define LDM4(r0, r1, r2, r3, addr) \
    asm volatile("ldmatrix.sync.aligned.m8n8.x4.shared.b16 {%0,%1,%2,%3}, [%4];" \
                 : "=r"(r0), "=r"(r1), "=r"(r2), "=r"(r3) : "r"(addr))

__device__ __forceinline__ void mma16816(float c[4], const uint32_t a[4], uint32_t b0, uint32_t b1) {
    asm volatile(
        "mma.sync.aligned.m16n8k16.row.col.f32.bf16.bf16.f32 "
        "{%0,%1,%2,%3},{%4,%5,%6,%7},{%8,%9},{%0,%1,%2,%3};"
        : "+f"(c[0]), "+f"(c[1]), "+f"(c[2]), "+f"(c[3])
        : "r"(a[0]), "r"(a[1]), "r"(a[2]), "r"(a[3]), "r"(b0), "r"(b1));
}

// ---------------------------------------------------------------------------
// Init: zero flags, reset counter, build interleaved topological cell list
// ---------------------------------------------------------------------------
__global__ void k_init()
{
    int i = blockIdx.x * blockDim.x + threadIdx.x;
    if (i < NCELL * 2) g_doneH[i] = 0;
    if (i == 0) g_next = 0;
    if (i == 1) {
        int idx = 0;
        for (int s = 0; s < 64; ++s) g_list[idx++] = make_int2(s, 0);   // inputs
        g_list[idx++] = make_int2(0, -1);                               // output 0
        for (int d = 2; d <= 126; ++d) {
            int s_lo = (d + 1) / 2;
            if (d - 63 > s_lo) s_lo = d - 63;
            int s_hi = (d - 1 < 63) ? d - 1 : 63;
            for (int s = s_lo; s <= s_hi; ++s)
                g_list[idx++] = make_int2(s, d - s);                    // wave cells
            if ((d & 1) == 0)
                g_list[idx++] = make_int2(d / 2, -1);                   // output s=d/2
        }
    }
}

// ---------------------------------------------------------------------------
// Persistent SANI kernel: dependency-driven task loop over all GEMM tiles.
// Wave tasks wait only on the A-source (diag d-2) up front; the critical
// B-source (diag d-1) is waited on at chunk BDEP_CHUNK, just before its
// loads enter the prefetch window — overlapping ~40% of the task with the
// producer and cutting the wavefront critical path.
// ---------------------------------------------------------------------------
__global__ void __launch_bounds__(256, 2)
k_sani(const float* __restrict__ b_in, const float* __restrict__ b_sani,
       const float* __restrict__ b_out)
{
    extern __shared__ __align__(128) char smem[];
    __shared__ int sh_task;

    const uint32_t sbase = smem_u32(smem);
    const int tid = threadIdx.x;
    const int wid = tid >> 5, lane = tid & 31;
    const int wm = wid & 1, wn = wid >> 1;       // warp grid 2(m) x 4(n)
    const int lr = lane >> 2;                    // 0..7
    const int lc2 = (lane & 3) * 2;              // 0,2,4,6

    // ldmatrix per-lane address components (byte offsets within a stage)
    const int arow = (lane & 7) + ((lane & 8) ? 8 : 0);
    const int akb  = ((lane & 16) ? 8 : 0) * 2;
    const uint32_t aHiOff0 = (uint32_t)(0 * TILE_B + (wm * 32 + 0 * 16 + arow) * RSB) + akb;
    const uint32_t aHiOff1 = (uint32_t)(0 * TILE_B + (wm * 32 + 1 * 16 + arow) * RSB) + akb;
    const uint32_t aLoOff0 = aHiOff0 + TILE_B;
    const uint32_t aLoOff1 = aHiOff1 + TILE_B;
    const int bnrow = wn * 16 + ((lane >> 4) & 1) * 8 + (lane & 7);
    const int bkb   = ((lane >> 3) & 1) * 8 * 2;
    const uint32_t bHiOff = (uint32_t)(2 * TILE_B + bnrow * RSB) + bkb;
    const uint32_t bLoOff = bHiOff + TILE_B;

    for (;;) {
        if (tid == 0) sh_task = atomicAdd(&g_next, 1);
        __syncthreads();
        const int t = sh_task;
        __syncthreads();          // protect sh_task before next iteration's write
        if (t >= NTASK) return;

        const int lcell = t >> 4;
        const int tile  = t & 15;
        const int mh = tile & 1;                 // M-half (64 rows)
        const int n0 = (tile >> 1) * 64;         // N-slice base (0..448)

        const int2 cc = g_list[lcell];
        const int s = cc.x, k = cc.y;
        const int type = (k < 0) ? 2 : (k == 0 ? 0 : 1);

        // ---- up-front dependency wait (A-source / diagonal only) ----
        const int* pB = nullptr;                 // deferred B-source dep
        if (tid == 0) {
            if (type == 1) {
                const int* p1 = &g_doneH[cellidx(s - 1, k - 1) * 2 + mh];
                while (ld_acq(p1) < 8) __nanosleep(64);
            } else if (type == 2) {
                const int* p = &g_doneH[cellidx(s, s) * 2 + mh];
                while (ld_acq(p) < 8) __nanosleep(64);
            }
        }
        if (type == 1) pB = &g_doneH[cellidx(s, k - 1) * 2 + mh];
        __syncthreads();

        // ---- operand pointers ----
        const bf16 *aH1, *aL1, *aH2 = nullptr, *aL2 = nullptr, *wH, *wL;
        const float* bias;
        int ldw, nch;
        size_t rowbase = (size_t)mh * 64 * 512;
        if (type == 0) {
            size_t xb = (size_t)s * 128 * 512 + rowbase;
            aH1 = g_Xhi + xb;  aL1 = g_Xlo + xb;
            wH = g_WinHi + (size_t)n0 * 512;  wL = g_WinLo + (size_t)n0 * 512;
            ldw = 512; nch = 16; bias = b_in;
        } else if (type == 1) {
            size_t pa = (size_t)cellidx(s - 1, k - 1) * CELLF + rowbase;
            size_t pb = (size_t)cellidx(s,     k - 1) * CELLF + rowbase;
            aH1 = g_Hhi + pa;  aL1 = g_Hlo + pa;
            aH2 = g_Hhi + pb;  aL2 = g_Hlo + pb;
            wH = g_Whi + (size_t)n0 * 1024;  wL = g_Wlo + (size_t)n0 * 1024;
            ldw = 1024; nch = 32; bias = b_sani;
        } else {
            size_t pa = (size_t)cellidx(s, s) * CELLF + rowbase;
            aH1 = g_Hhi + pa;  aL1 = g_Hlo + pa;
            wH = g_WoutHi + (size_t)n0 * 512;  wL = g_WoutLo + (size_t)n0 * 512;
            ldw = 512; nch = 16; bias = b_out;
        }

        // ---- GEMM: 64x64, K = nch*32, 3-product bf16 split ----
        float acc[2][2][4];
        #pragma unroll
        for (int i = 0; i < 2; ++i)
            #pragma unroll
            for (int j = 0; j < 2; ++j)
                #pragma unroll
                for (int q = 0; q < 4; ++q) acc[i][j][q] = 0.f;

        auto issue = [&](int c) {
            const bf16* ah; const bf16* al; int ka;
            if (c < 16) { ah = aH1; al = aL1; ka = c * 32; }
            else        { ah = aH2; al = aL2; ka = (c - 16) * 32; }
            const int kw = c * 32;
            const uint32_t sm = sbase + (uint32_t)(c & (NSTAGE - 1)) * STAGE_B;
            const int row = tid >> 2, seg = tid & 3;
            const uint32_t off = (uint32_t)(row * RSB + seg * 16);
            cpa16(sm + 0 * TILE_B + off, ah + (size_t)row * 512 + ka + seg * 8);
            cpa16(sm + 1 * TILE_B + off, al + (size_t)row * 512 + ka + seg * 8);
            cpa16(sm + 2 * TILE_B + off, wH + (size_t)row * ldw + kw + seg * 8);
            cpa16(sm + 3 * TILE_B + off, wL + (size_t)row * ldw + kw + seg * 8);
            cp_commit();
        };

        issue(0); issue(1); issue(2);

        for (int c = 0; c < nch; ++c) {
            cp_wait2();           // 3 groups outstanding -> group c complete
            // Deferred B-source wait: must complete before issue(16), which
            // happens at the end of chunk BDEP_CHUNK. The barrier below
            // broadcasts the completed wait to all threads.
            if (c == BDEP_CHUNK && pB && tid == 0)
                while (ld_acq(pB) < 8) __nanosleep(64);
            __syncthreads();      // one barrier per chunk

            const uint32_t stg = sbase + (uint32_t)(c & (NSTAGE - 1)) * STAGE_B;
            #pragma unroll
            for (int ks = 0; ks < 2; ++ks) {
                const uint32_t kb = stg + ks * 32;   // k0*2 bytes
                uint32_t ah[2][4], al[2][4], bh[4], bl[4];
                LDM4(ah[0][0], ah[0][1], ah[0][2], ah[0][3], kb + aHiOff0);
                LDM4(ah[1][0], ah[1][1], ah[1][2], ah[1][3], kb + aHiOff1);
                LDM4(al[0][0], al[0][1], al[0][2], al[0][3], kb + aLoOff0);
                LDM4(al[1][0], al[1][1], al[1][2], al[1][3], kb + aLoOff1);
                LDM4(bh[0], bh[1], bh[2], bh[3], kb + bHiOff);
                LDM4(bl[0], bl[1], bl[2], bl[3], kb + bLoOff);
                // product-major: 4 independent accumulators between reuses
                #pragma unroll
                for (int mi = 0; mi < 2; ++mi)
                    #pragma unroll
                    for (int ni = 0; ni < 2; ++ni)
                        mma16816(acc[mi][ni], ah[mi], bh[ni * 2], bh[ni * 2 + 1]);
                #pragma unroll
                for (int mi = 0; mi < 2; ++mi)
                    #pragma unroll
                    for (int ni = 0; ni < 2; ++ni)
                        mma16816(acc[mi][ni], ah[mi], bl[ni * 2], bl[ni * 2 + 1]);
                #pragma unroll
                for (int mi = 0; mi < 2; ++mi)
                    #pragma unroll
                    for (int ni = 0; ni < 2; ++ni)
                        mma16816(acc[mi][ni], al[mi], bh[ni * 2], bh[ni * 2 + 1]);
            }
            if (c + 3 < nch) issue(c + 3);
            else cp_commit();     // empty group keeps wait-depth uniform
        }

        // ---- epilogue ----
        int dstCell = (type == 0) ? cellidx(s, 0) : (type == 1 ? cellidx(s, k) : -1);
        bf16* outHi = (dstCell >= 0) ? g_Hhi + (size_t)dstCell * CELLF : nullptr;
        bf16* outLo = (dstCell >= 0) ? g_Hlo + (size_t)dstCell * CELLF : nullptr;
        float* outF = (type == 2) ? g_y + (size_t)s * 128 * 512 : nullptr;

        #pragma unroll
        for (int mi = 0; mi < 2; ++mi) {
            const int r0 = mh * 64 + wm * 32 + mi * 16 + lr;   // row within 128
            #pragma unroll
            for (int ni = 0; ni < 2; ++ni) {
                const int ccol = n0 + wn * 16 + ni * 8 + lc2;
                const float bx = bias[ccol];
                const float by = bias[ccol + 1];
                #pragma unroll
                for (int half = 0; half < 2; ++half) {
                    const int r = r0 + half * 8;
                    const float v0 = acc[mi][ni][half * 2]     + bx;
                    const float v1 = acc[mi][ni][half * 2 + 1] + by;
                    if (outF) {
                        float2 fv; fv.x = v0; fv.y = v1;
                        *reinterpret_cast<float2*>(outF + (size_t)r * 512 + ccol) = fv;
                    } else {
                        bf16 h0 = __float2bfloat16(v0), h1 = __float2bfloat16(v1);
                        bf16 e0 = __float2bfloat16(v0 - __bfloat162float(h0));
                        bf16 e1 = __float2bfloat16(v1 - __bfloat162float(h1));
                        __nv_bfloat162 hp; hp.x = h0; hp.y = h1;
                        __nv_bfloat162 lp; lp.x = e0; lp.y = e1;
                        *reinterpret_cast<__nv_bfloat162*>(outHi + (size_t)r * 512 + ccol) = hp;
                        *reinterpret_cast<__nv_bfloat162*>(outLo + (size_t)r * 512 + ccol) = lp;
                    }
                }
            }
        }

        // ---- signal completion (per cell half) ----
        if (dstCell >= 0) {
            __threadfence();
            __syncthreads();
            if (tid == 0) red_rel(&g_doneH[dstCell * 2 + mh]);
        }
    }
}

// ---------------------------------------------------------------------------
// Prep kernels
// ---------------------------------------------------------------------------
__global__ void k_split_sani(const float* __restrict__ src) {
    int i = blockIdx.x * blockDim.x + threadIdx.x;
    float v = src[i];
    bf16 h = __float2bfloat16(v);
    g_Whi[i] = h;
    g_Wlo[i] = __float2bfloat16(v - __bfloat162float(h));
}
__global__ void k_split_in(const float* __restrict__ src) {
    int i = blockIdx.x * blockDim.x + threadIdx.x;
    float v = src[i];
    bf16 h = __float2bfloat16(v);
    g_WinHi[i] = h;
    g_WinLo[i] = __float2bfloat16(v - __bfloat162float(h));
}
__global__ void k_split_out(const float* __restrict__ src) {
    int i = blockIdx.x * blockDim.x + threadIdx.x;
    float v = src[i];
    bf16 h = __float2bfloat16(v);
    g_WoutHi[i] = h;
    g_WoutLo[i] = __float2bfloat16(v - __bfloat162float(h));
}

__global__ void __launch_bounds__(256)
k_gather(const int* __restrict__ labels, const float* __restrict__ emb)
{
    const int r = blockIdx.x;            // r = s*128 + n
    const int n = r & 127, s = r >> 7;
    const float* row = emb + (size_t)labels[n * LL + s] * EE;
    const int e = threadIdx.x * 2;
    float2 v = *reinterpret_cast<const float2*>(row + e);
    bf16 h0 = __float2bfloat16(v.x), h1 = __float2bfloat16(v.y);
    bf16 l0 = __float2bfloat16(v.x - __bfloat162float(h0));
    bf16 l1 = __float2bfloat16(v.y - __bfloat162float(h1));
    __nv_bfloat162 hp; hp.x = h0; hp.y = h1;
    __nv_bfloat162 lp; lp.x = l0; lp.y = l1;
    *reinterpret_cast<__nv_bfloat162*>(g_Xhi + (size_t)r * EE + e) = hp;
    *reinterpret_cast<__nv_bfloat162*>(g_Xlo + (size_t)r * EE + e) = lp;
}

// ---------------------------------------------------------------------------
// Loss (flat row r = s*128+n; reshape(N,L,E) reads flat row n*64+l)
// ---------------------------------------------------------------------------
__global__ void __launch_bounds__(512)
k_loss(const int* __restrict__ labels, const float* __restrict__ emb_table)
{
    __shared__ float red[512];
    const int n = blockIdx.x;
    const int e = threadIdx.x;
    const float* yb = g_y + (size_t)n * LL * EE + e;

    float m = -1e30f;
    #pragma unroll
    for (int l = 0; l < LL; ++l) m = fmaxf(m, yb[(size_t)l * EE]);

    float se = 0.f, dot = 0.f, sume = 0.f;
    #pragma unroll
    for (int l = 0; l < LL; ++l) {
        float yv = yb[(size_t)l * EE];
        float ev = emb_table[(size_t)labels[n * LL + l] * EE + e];
        se   += expf(yv - m);
        dot  += ev * yv;
        sume += ev;
    }
    float lse = m + logf(se);
    red[e] = dot - sume * lse;
    __syncthreads();
    for (int stride = 256; stride > 0; stride >>= 1) {
        if (e < stride) red[e] += red[e + stride];
        __syncthreads();
    }
    if (e == 0) g_part[n] = red[0];
}

__global__ void k_final(float* __restrict__ out)
{
    __shared__ float red[128];
    const int t = threadIdx.x;
    red[t] = g_part[t];
    __syncthreads();
    for (int stride = 64; stride > 0; stride >>= 1) {
        if (t < stride) red[t] += red[t + stride];
        __syncthreads();
    }
    if (t == 0) out[0] = -red[0] / (float)(NB * EE);
}

// ---------------------------------------------------------------------------
extern "C" void kernel_launch(void* const* d_in, const int* in_sizes, int n_in,
                              void* d_out, int out_size)
{
    const int*   labels    = (const int*)  d_in[0];
    const float* emb_table = (const float*)d_in[1];
    const float* W_in      = (const float*)d_in[2];
    const float* b_in      = (const float*)d_in[3];
    const float* W_sani    = (const float*)d_in[4];
    const float* b_sani    = (const float*)d_in[5];
    const float* W_out     = (const float*)d_in[6];
    const float* b_out     = (const float*)d_in[7];

    // Unconditional each call (no static guards; idempotent non-stream API)
    cudaFuncSetAttribute(k_sani, cudaFuncAttributeMaxDynamicSharedMemorySize, GSMEM);

    // Scheduling state reset + task list build
    k_init<<<17, 256>>>();

    // Weight splits + embedding gather
    k_split_sani<<<2048, 256>>>(W_sani);
    k_split_in<<<1024, 256>>>(W_in);
    k_split_out<<<1024, 256>>>(W_out);
    k_gather<<<8192, 256>>>(labels, emb_table);

    // All GEMM work: one persistent dependency-driven kernel (2 CTAs/SM)
    k_sani<<<NCTA, 256, GSMEM>>>(b_in, b_sani, b_out);

    // Loss
    k_loss<<<NB, 512>>>(labels, emb_table);
    k_final<<<1, 128>>>((float*)d_out);
}

// round 15
// speedup vs baseline: 4.1635x; 1.3255x over previous
#include <cuda_runtime.h>
#include <cuda_bf16.h>
#include <cstdint>

// ---------------------------------------------------------------------------
// Problem constants
// ---------------------------------------------------------------------------
#define NB   128
#define LL   64
#define HH   512
#define EE   512
#define NCELL 2080
#define CELLF 65536   // 128*512

typedef __nv_bfloat16 bf16;

// Tile config: task = 64(M) x 64(N), K full. 16 tasks per logical cell.
// 8 warps: 2(m) x 4(n), warp tile 32x16.
// Precision: bf16 activations (A = hi only), fp32-pair weights (Whi + Wlo).
//   C = Ahi@Whi + Ahi@Wlo  (2-product split)
#define RSB    80                 // smem row stride bytes (64 data + 16 pad)
#define TILE_B (64 * RSB)         // 5120 bytes per operand tile
#define STAGE_B (3 * TILE_B)      // Ahi, Whi, Wlo = 15360
#define NSTAGE 6
#define GSMEM (NSTAGE * STAGE_B)  // 92160 dynamic (2 CTAs/SM -> 184KB)

#define NLCELL 2144               // 64 input + 2016 wave + 64 output
#define NTASK  (NLCELL * 16)
#define NCTA   296                // 2 per SM

// B-source dependency wait chunk: loads for chunk 16 are prefetched at the
// end of chunk 11 (depth-5 lookahead), so the wait must complete by then.
#define BDEP_CHUNK 11

// ---------------------------------------------------------------------------
// Device scratch (allocation-free)
// ---------------------------------------------------------------------------
__device__ bf16 g_Hhi[(size_t)NCELL * CELLF];    // 273 MB (activations, bf16)
__device__ bf16 g_Whi[HH * 2 * HH], g_Wlo[HH * 2 * HH];
__device__ bf16 g_WinHi[HH * EE],  g_WinLo[HH * EE];
__device__ bf16 g_WoutHi[EE * HH], g_WoutLo[EE * HH];
__device__ bf16 g_Xhi[8192 * EE];                // gathered embeddings (bf16)
__device__ float g_y[8192 * 512];
__device__ float g_part[NB];

// Scheduling state
__device__ int  g_next;
__device__ int  g_doneH[NCELL * 2];   // completed tiles per (cell, m-half); 8 = ready
__device__ int2 g_list[NLCELL];       // (s, k); k==0 input, k>0 wave, k==-1 output

__device__ __forceinline__ int cellidx(int s, int k) { return s * (s + 1) / 2 + k; }

__device__ __forceinline__ uint32_t smem_u32(const void* p) {
    uint32_t a;
    asm("{ .reg .u64 t; cvta.to.shared.u64 t, %1; cvt.u32.u64 %0, t; }" : "=r"(a) : "l"(p));
    return a;
}
__device__ __forceinline__ void cpa16(uint32_t dst, const void* src) {
    asm volatile("cp.async.ca.shared.global [%0], [%1], 16;" :: "r"(dst), "l"(src));
}
__device__ __forceinline__ void cp_commit() { asm volatile("cp.async.commit_group;" ::: "memory"); }
__device__ __forceinline__ void cp_wait4()  { asm volatile("cp.async.wait_group 4;" ::: "memory"); }

__device__ __forceinline__ int ld_acq(const int* p) {
    int v;
    asm volatile("ld.acquire.gpu.global.b32 %0, [%1];" : "=r"(v) : "l"(p));
    return v;
}
__device__ __forceinline__ void red_rel(int* p) {
    asm volatile("red.release.gpu.global.add.s32 [%0], 1;" :: "l"(p));
}

#define LDM4(r0, r1, r2, r3, addr) \
    asm volatile("ldmatrix.sync.aligned.m8n8.x4.shared.b16 {%0,%1,%2,%3}, [%4];" \
                 : "=r"(r0), "=r"(r1), "=r"(r2), "=r"(r3) : "r"(addr))

__device__ __forceinline__ void mma16816(float c[4], const uint32_t a[4], uint32_t b0, uint32_t b1) {
    asm volatile(
        "mma.sync.aligned.m16n8k16.row.col.f32.bf16.bf16.f32 "
        "{%0,%1,%2,%3},{%4,%5,%6,%7},{%8,%9},{%0,%1,%2,%3};"
        : "+f"(c[0]), "+f"(c[1]), "+f"(c[2]), "+f"(c[3])
        : "r"(a[0]), "r"(a[1]), "r"(a[2]), "r"(a[3]), "r"(b0), "r"(b1));
}

// ---------------------------------------------------------------------------
// Init: zero flags, reset counter, build interleaved topological cell list
// ---------------------------------------------------------------------------
__global__ void k_init()
{
    int i = blockIdx.x * blockDim.x + threadIdx.x;
    if (i < NCELL * 2) g_doneH[i] = 0;
    if (i == 0) g_next = 0;
    if (i == 1) {
        int idx = 0;
        for (int s = 0; s < 64; ++s) g_list[idx++] = make_int2(s, 0);   // inputs
        g_list[idx++] = make_int2(0, -1);                               // output 0
        for (int d = 2; d <= 126; ++d) {
            int s_lo = (d + 1) / 2;
            if (d - 63 > s_lo) s_lo = d - 63;
            int s_hi = (d - 1 < 63) ? d - 1 : 63;
            for (int s = s_lo; s <= s_hi; ++s)
                g_list[idx++] = make_int2(s, d - s);                    // wave cells
            if ((d & 1) == 0)
                g_list[idx++] = make_int2(d / 2, -1);                   // output s=d/2
        }
    }
}

// ---------------------------------------------------------------------------
// Persistent SANI kernel: dependency-driven task loop over all GEMM tiles.
// Wave tasks wait on the A-source (diag d-2) up front; the critical B-source
// (diag d-1) wait is deferred to chunk BDEP_CHUNK (just before its loads
// enter the depth-5 prefetch window).
// ---------------------------------------------------------------------------
__global__ void __launch_bounds__(256, 2)
k_sani(const float* __restrict__ b_in, const float* __restrict__ b_sani,
       const float* __restrict__ b_out)
{
    extern __shared__ __align__(128) char smem[];
    __shared__ int sh_task;

    const uint32_t sbase = smem_u32(smem);
    const int tid = threadIdx.x;
    const int wid = tid >> 5, lane = tid & 31;
    const int wm = wid & 1, wn = wid >> 1;       // warp grid 2(m) x 4(n)
    const int lr = lane >> 2;                    // 0..7
    const int lc2 = (lane & 3) * 2;              // 0,2,4,6

    // ldmatrix per-lane address components (byte offsets within a stage)
    const int arow = (lane & 7) + ((lane & 8) ? 8 : 0);
    const int akb  = ((lane & 16) ? 8 : 0) * 2;
    const uint32_t aHiOff0 = (uint32_t)(0 * TILE_B + (wm * 32 + 0 * 16 + arow) * RSB) + akb;
    const uint32_t aHiOff1 = (uint32_t)(0 * TILE_B + (wm * 32 + 1 * 16 + arow) * RSB) + akb;
    const int bnrow = wn * 16 + ((lane >> 4) & 1) * 8 + (lane & 7);
    const int bkb   = ((lane >> 3) & 1) * 8 * 2;
    const uint32_t bHiOff = (uint32_t)(1 * TILE_B + bnrow * RSB) + bkb;
    const uint32_t bLoOff = (uint32_t)(2 * TILE_B + bnrow * RSB) + bkb;

    for (;;) {
        if (tid == 0) sh_task = atomicAdd(&g_next, 1);
        __syncthreads();
        const int t = sh_task;
        __syncthreads();          // protect sh_task before next iteration's write
        if (t >= NTASK) return;

        const int lcell = t >> 4;
        const int tile  = t & 15;
        const int mh = tile & 1;                 // M-half (64 rows)
        const int n0 = (tile >> 1) * 64;         // N-slice base (0..448)

        const int2 cc = g_list[lcell];
        const int s = cc.x, k = cc.y;
        const int type = (k < 0) ? 2 : (k == 0 ? 0 : 1);

        // ---- up-front dependency wait (A-source / diagonal only) ----
        const int* pB = nullptr;                 // deferred B-source dep
        if (tid == 0) {
            if (type == 1) {
                const int* p1 = &g_doneH[cellidx(s - 1, k - 1) * 2 + mh];
                while (ld_acq(p1) < 8) __nanosleep(64);
            } else if (type == 2) {
                const int* p = &g_doneH[cellidx(s, s) * 2 + mh];
                while (ld_acq(p) < 8) __nanosleep(64);
            }
        }
        if (type == 1) pB = &g_doneH[cellidx(s, k - 1) * 2 + mh];
        __syncthreads();

        // ---- operand pointers ----
        const bf16 *aH1, *aH2 = nullptr, *wH, *wL;
        const float* bias;
        int ldw, nch;
        size_t rowbase = (size_t)mh * 64 * 512;
        if (type == 0) {
            size_t xb = (size_t)s * 128 * 512 + rowbase;
            aH1 = g_Xhi + xb;
            wH = g_WinHi + (size_t)n0 * 512;  wL = g_WinLo + (size_t)n0 * 512;
            ldw = 512; nch = 16; bias = b_in;
        } else if (type == 1) {
            size_t pa = (size_t)cellidx(s - 1, k - 1) * CELLF + rowbase;
            size_t pb = (size_t)cellidx(s,     k - 1) * CELLF + rowbase;
            aH1 = g_Hhi + pa;
            aH2 = g_Hhi + pb;
            wH = g_Whi + (size_t)n0 * 1024;  wL = g_Wlo + (size_t)n0 * 1024;
            ldw = 1024; nch = 32; bias = b_sani;
        } else {
            size_t pa = (size_t)cellidx(s, s) * CELLF + rowbase;
            aH1 = g_Hhi + pa;
            wH = g_WoutHi + (size_t)n0 * 512;  wL = g_WoutLo + (size_t)n0 * 512;
            ldw = 512; nch = 16; bias = b_out;
        }

        // ---- GEMM: 64x64, K = nch*32, 2-product split (Ahi@Whi + Ahi@Wlo) --
        float acc[2][2][4];
        #pragma unroll
        for (int i = 0; i < 2; ++i)
            #pragma unroll
            for (int j = 0; j < 2; ++j)
                #pragma unroll
                for (int q = 0; q < 4; ++q) acc[i][j][q] = 0.f;

        auto issue = [&](int c) {
            const bf16* ah; int ka;
            if (c < 16) { ah = aH1; ka = c * 32; }
            else        { ah = aH2; ka = (c - 16) * 32; }
            const int kw = c * 32;
            const uint32_t sm = sbase + (uint32_t)(c % NSTAGE) * STAGE_B;
            const int row = tid >> 2, seg = tid & 3;
            const uint32_t off = (uint32_t)(row * RSB + seg * 16);
            cpa16(sm + 0 * TILE_B + off, ah + (size_t)row * 512 + ka + seg * 8);
            cpa16(sm + 1 * TILE_B + off, wH + (size_t)row * ldw + kw + seg * 8);
            cpa16(sm + 2 * TILE_B + off, wL + (size_t)row * ldw + kw + seg * 8);
            cp_commit();
        };

        issue(0); issue(1); issue(2); issue(3); issue(4);

        for (int c = 0; c < nch; ++c) {
            cp_wait4();           // 5 groups outstanding -> group c complete
            // Deferred B-source wait: must complete before issue(16), which
            // happens at the end of chunk BDEP_CHUNK (depth-5 lookahead).
            if (c == BDEP_CHUNK && pB && tid == 0)
                while (ld_acq(pB) < 8) __nanosleep(64);
            __syncthreads();      // one barrier per chunk; issuing below
                                  // targets stage (c-1)%NSTAGE, fully consumed
                                  // before this barrier

            const uint32_t stg = sbase + (uint32_t)(c % NSTAGE) * STAGE_B;
            #pragma unroll
            for (int ks = 0; ks < 2; ++ks) {
                const uint32_t kb = stg + ks * 32;   // k0*2 bytes
                uint32_t ah[2][4], bh[4], bl[4];
                LDM4(ah[0][0], ah[0][1], ah[0][2], ah[0][3], kb + aHiOff0);
                LDM4(ah[1][0], ah[1][1], ah[1][2], ah[1][3], kb + aHiOff1);
                LDM4(bh[0], bh[1], bh[2], bh[3], kb + bHiOff);
                LDM4(bl[0], bl[1], bl[2], bl[3], kb + bLoOff);
                // product-major: 4 independent accumulators between reuses
                #pragma unroll
                for (int mi = 0; mi < 2; ++mi)
                    #pragma unroll
                    for (int ni = 0; ni < 2; ++ni)
                        mma16816(acc[mi][ni], ah[mi], bh[ni * 2], bh[ni * 2 + 1]);
                #pragma unroll
                for (int mi = 0; mi < 2; ++mi)
                    #pragma unroll
                    for (int ni = 0; ni < 2; ++ni)
                        mma16816(acc[mi][ni], ah[mi], bl[ni * 2], bl[ni * 2 + 1]);
            }
            if (c + 5 < nch) issue(c + 5);
            else cp_commit();     // empty group keeps wait-depth uniform
        }

        // ---- epilogue ----
        int dstCell = (type == 0) ? cellidx(s, 0) : (type == 1 ? cellidx(s, k) : -1);
        bf16* outHi = (dstCell >= 0) ? g_Hhi + (size_t)dstCell * CELLF : nullptr;
        float* outF = (type == 2) ? g_y + (size_t)s * 128 * 512 : nullptr;

        #pragma unroll
        for (int mi = 0; mi < 2; ++mi) {
            const int r0 = mh * 64 + wm * 32 + mi * 16 + lr;   // row within 128
            #pragma unroll
            for (int ni = 0; ni < 2; ++ni) {
                const int ccol = n0 + wn * 16 + ni * 8 + lc2;
                const float bx = bias[ccol];
                const float by = bias[ccol + 1];
                #pragma unroll
                for (int half = 0; half < 2; ++half) {
                    const int r = r0 + half * 8;
                    const float v0 = acc[mi][ni][half * 2]     + bx;
                    const float v1 = acc[mi][ni][half * 2 + 1] + by;
                    if (outF) {
                        float2 fv; fv.x = v0; fv.y = v1;
                        *reinterpret_cast<float2*>(outF + (size_t)r * 512 + ccol) = fv;
                    } else {
                        __nv_bfloat162 hp;
                        hp.x = __float2bfloat16(v0);
                        hp.y = __float2bfloat16(v1);
                        *reinterpret_cast<__nv_bfloat162*>(outHi + (size_t)r * 512 + ccol) = hp;
                    }
                }
            }
        }

        // ---- signal completion (per cell half) ----
        if (dstCell >= 0) {
            __threadfence();
            __syncthreads();
            if (tid == 0) red_rel(&g_doneH[dstCell * 2 + mh]);
        }
    }
}

// ---------------------------------------------------------------------------
// Prep kernels (weights split to fp32-pair; activations bf16 only)
// ---------------------------------------------------------------------------
__global__ void k_split_sani(const float* __restrict__ src) {
    int i = blockIdx.x * blockDim.x + threadIdx.x;
    float v = src[i];
    bf16 h = __float2bfloat16(v);
    g_Whi[i] = h;
    g_Wlo[i] = __float2bfloat16(v - __bfloat162float(h));
}
__global__ void k_split_in(const float* __restrict__ src) {
    int i = blockIdx.x * blockDim.x + threadIdx.x;
    float v = src[i];
    bf16 h = __float2bfloat16(v);
    g_WinHi[i] = h;
    g_WinLo[i] = __float2bfloat16(v - __bfloat162float(h));
}
__global__ void k_split_out(const float* __restrict__ src) {
    int i = blockIdx.x * blockDim.x + threadIdx.x;
    float v = src[i];
    bf16 h = __float2bfloat16(v);
    g_WoutHi[i] = h;
    g_WoutLo[i] = __float2bfloat16(v - __bfloat162float(h));
}

__global__ void __launch_bounds__(256)
k_gather(const int* __restrict__ labels, const float* __restrict__ emb)
{
    const int r = blockIdx.x;            // r = s*128 + n
    const int n = r & 127, s = r >> 7;
    const float* row = emb + (size_t)labels[n * LL + s] * EE;
    const int e = threadIdx.x * 2;
    float2 v = *reinterpret_cast<const float2*>(row + e);
    __nv_bfloat162 hp;
    hp.x = __float2bfloat16(v.x);
    hp.y = __float2bfloat16(v.y);
    *reinterpret_cast<__nv_bfloat162*>(g_Xhi + (size_t)r * EE + e) = hp;
}

// ---------------------------------------------------------------------------
// Loss (flat row r = s*128+n; reshape(N,L,E) reads flat row n*64+l)
// ---------------------------------------------------------------------------
__global__ void __launch_bounds__(512)
k_loss(const int* __restrict__ labels, const float* __restrict__ emb_table)
{
    __shared__ float red[512];
    const int n = blockIdx.x;
    const int e = threadIdx.x;
    const float* yb = g_y + (size_t)n * LL * EE + e;

    float m = -1e30f;
    #pragma unroll
    for (int l = 0; l < LL; ++l) m = fmaxf(m, yb[(size_t)l * EE]);

    float se = 0.f, dot = 0.f, sume = 0.f;
    #pragma unroll
    for (int l = 0; l < LL; ++l) {
        float yv = yb[(size_t)l * EE];
        float ev = emb_table[(size_t)labels[n * LL + l] * EE + e];
        se   += expf(yv - m);
        dot  += ev * yv;
        sume += ev;
    }
    float lse = m + logf(se);
    red[e] = dot - sume * lse;
    __syncthreads();
    for (int stride = 256; stride > 0; stride >>= 1) {
        if (e < stride) red[e] += red[e + stride];
        __syncthreads();
    }
    if (e == 0) g_part[n] = red[0];
}

__global__ void k_final(float* __restrict__ out)
{
    __shared__ float red[128];
    const int t = threadIdx.x;
    red[t] = g_part[t];
    __syncthreads();
    for (int stride = 64; stride > 0; stride >>= 1) {
        if (t < stride) red[t] += red[t + stride];
        __syncthreads();
    }
    if (t == 0) out[0] = -red[0] / (float)(NB * EE);
}

// ---------------------------------------------------------------------------
extern "C" void kernel_launch(void* const* d_in, const int* in_sizes, int n_in,
                              void* d_out, int out_size)
{
    const int*   labels    = (const int*)  d_in[0];
    const float* emb_table = (const float*)d_in[1];
    const float* W_in      = (const float*)d_in[2];
    const float* b_in      = (const float*)d_in[3];
    const float* W_sani    = (const float*)d_in[4];
    const float* b_sani    = (const float*)d_in[5];
    const float* W_out     = (const float*)d_in[6];
    const float* b_out     = (const float*)d_in[7];

    // Unconditional each call (no static guards; idempotent non-stream API)
    cudaFuncSetAttribute(k_sani, cudaFuncAttributeMaxDynamicSharedMemorySize, GSMEM);

    // Scheduling state reset + task list build
    k_init<<<17, 256>>>();

    // Weight splits + embedding gather
    k_split_sani<<<2048, 256>>>(W_sani);
    k_split_in<<<1024, 256>>>(W_in);
    k_split_out<<<1024, 256>>>(W_out);
    k_gather<<<8192, 256>>>(labels, emb_table);

    // All GEMM work: one persistent dependency-driven kernel (2 CTAs/SM)
    k_sani<<<NCTA, 256, GSMEM>>>(b_in, b_sani, b_out);

    // Loss
    k_loss<<<NB, 512>>>(labels, emb_table);
    k_final<<<1, 128>>>((float*)d_out);
}

// round 16
// speedup vs baseline: 5.1356x; 1.2335x over previous
#include <cuda_runtime.h>
#include <cuda_bf16.h>
#include <cstdint>

// ---------------------------------------------------------------------------
// Problem constants
// ---------------------------------------------------------------------------
#define NB   128
#define LL   64
#define HH   512
#define EE   512
#define NCELL 2080
#define CELLF 65536   // 128*512

typedef __nv_bfloat16 bf16;

// Tile config: task = 64(M) x 64(N), K full. 16 tasks per logical cell.
// 8 warps: 2(m) x 4(n), warp tile 32x16.
// Precision: bf16 activations (A = hi only), fp32-pair weights (Whi + Wlo).
//   C = Ahi@Whi + Ahi@Wlo  (2-product split)
// K-chunk = 64 elements (128B rows): halves barriers/commit groups vs K=32.
#define RSB    144                // smem row stride bytes (128 data + 16 pad)
#define TILE_B (64 * RSB)         // 9216 bytes per operand tile
#define STAGE_B (3 * TILE_B)      // Ahi, Whi, Wlo = 27648
#define NSTAGE 4
#define GSMEM (NSTAGE * STAGE_B)  // 110592 dynamic (2 CTAs/SM -> 221KB)

#define NLCELL 2144               // 64 input + 2016 wave + 64 output
#define NTASK  (NLCELL * 16)
#define NCTA   296                // 2 per SM

// B-source dependency wait chunk: loads for chunk 8 (first B chunk) are
// prefetched at the end of chunk 5 (depth-3 lookahead).
#define BDEP_CHUNK 5

// ---------------------------------------------------------------------------
// Device scratch (allocation-free)
// ---------------------------------------------------------------------------
__device__ bf16 g_Hhi[(size_t)NCELL * CELLF];    // 273 MB (activations, bf16)
__device__ bf16 g_Whi[HH * 2 * HH], g_Wlo[HH * 2 * HH];
__device__ bf16 g_WinHi[HH * EE],  g_WinLo[HH * EE];
__device__ bf16 g_WoutHi[EE * HH], g_WoutLo[EE * HH];
__device__ bf16 g_Xhi[8192 * EE];                // gathered embeddings (bf16)
__device__ float g_y[8192 * 512];
__device__ float g_part[NB];

// Scheduling state
__device__ int  g_next;
__device__ int  g_doneH[NCELL * 2];   // completed tiles per (cell, m-half); 8 = ready
__device__ int2 g_list[NLCELL];       // (s, k); k==0 input, k>0 wave, k==-1 output

__device__ __forceinline__ int cellidx(int s, int k) { return s * (s + 1) / 2 + k; }

__device__ __forceinline__ uint32_t smem_u32(const void* p) {
    uint32_t a;
    asm("{ .reg .u64 t; cvta.to.shared.u64 t, %1; cvt.u32.u64 %0, t; }" : "=r"(a) : "l"(p));
    return a;
}
__device__ __forceinline__ void cpa16(uint32_t dst, const void* src) {
    asm volatile("cp.async.ca.shared.global [%0], [%1], 16;" :: "r"(dst), "l"(src));
}
__device__ __forceinline__ void cp_commit() { asm volatile("cp.async.commit_group;" ::: "memory"); }
__device__ __forceinline__ void cp_wait2()  { asm volatile("cp.async.wait_group 2;" ::: "memory"); }

__device__ __forceinline__ int ld_acq(const int* p) {
    int v;
    asm volatile("ld.acquire.gpu.global.b32 %0, [%1];" : "=r"(v) : "l"(p));
    return v;
}
__device__ __forceinline__ void red_rel(int* p) {
    asm volatile("red.release.gpu.global.add.s32 [%0], 1;" :: "l"(p));
}

#define LDM4(r0, r1, r2, r3, addr) \
    asm volatile("ldmatrix.sync.aligned.m8n8.x4.shared.b16 {%0,%1,%2,%3}, [%4];" \
                 : "=r"(r0), "=r"(r1), "=r"(r2), "=r"(r3) : "r"(addr))

__device__ __forceinline__ void mma16816(float c[4], const uint32_t a[4], uint32_t b0, uint32_t b1) {
    asm volatile(
        "mma.sync.aligned.m16n8k16.row.col.f32.bf16.bf16.f32 "
        "{%0,%1,%2,%3},{%4,%5,%6,%7},{%8,%9},{%0,%1,%2,%3};"
        : "+f"(c[0]), "+f"(c[1]), "+f"(c[2]), "+f"(c[3])
        : "r"(a[0]), "r"(a[1]), "r"(a[2]), "r"(a[3]), "r"(b0), "r"(b1));
}

// ---------------------------------------------------------------------------
// Init: zero flags, reset counter, build interleaved topological cell list
// ---------------------------------------------------------------------------
__global__ void k_init()
{
    int i = blockIdx.x * blockDim.x + threadIdx.x;
    if (i < NCELL * 2) g_doneH[i] = 0;
    if (i == 0) g_next = 0;
    if (i == 1) {
        int idx = 0;
        for (int s = 0; s < 64; ++s) g_list[idx++] = make_int2(s, 0);   // inputs
        g_list[idx++] = make_int2(0, -1);                               // output 0
        for (int d = 2; d <= 126; ++d) {
            int s_lo = (d + 1) / 2;
            if (d - 63 > s_lo) s_lo = d - 63;
            int s_hi = (d - 1 < 63) ? d - 1 : 63;
            for (int s = s_lo; s <= s_hi; ++s)
                g_list[idx++] = make_int2(s, d - s);                    // wave cells
            if ((d & 1) == 0)
                g_list[idx++] = make_int2(d / 2, -1);                   // output s=d/2
        }
    }
}

// ---------------------------------------------------------------------------
// Persistent SANI kernel: dependency-driven task loop over all GEMM tiles.
// Wave tasks wait on the A-source (diag d-2) up front; the critical B-source
// (diag d-1) wait is deferred to chunk BDEP_CHUNK (just before its loads
// enter the depth-3 prefetch window).
// ---------------------------------------------------------------------------
__global__ void __launch_bounds__(256, 2)
k_sani(const float* __restrict__ b_in, const float* __restrict__ b_sani,
       const float* __restrict__ b_out)
{
    extern __shared__ __align__(128) char smem[];
    __shared__ int sh_task;

    const uint32_t sbase = smem_u32(smem);
    const int tid = threadIdx.x;
    const int wid = tid >> 5, lane = tid & 31;
    const int wm = wid & 1, wn = wid >> 1;       // warp grid 2(m) x 4(n)
    const int lr = lane >> 2;                    // 0..7
    const int lc2 = (lane & 3) * 2;              // 0,2,4,6

    // ldmatrix per-lane address components (byte offsets within a stage)
    const int arow = (lane & 7) + ((lane & 8) ? 8 : 0);
    const int akb  = (lane & 16) ? 16 : 0;       // second 8x8: k+8 -> +16B
    const uint32_t aHiOff0 = (uint32_t)(0 * TILE_B + (wm * 32 + 0 * 16 + arow) * RSB) + akb;
    const uint32_t aHiOff1 = (uint32_t)(0 * TILE_B + (wm * 32 + 1 * 16 + arow) * RSB) + akb;
    const int bnrow = wn * 16 + ((lane >> 4) & 1) * 8 + (lane & 7);
    const int bkb   = ((lane >> 3) & 1) * 16;
    const uint32_t bHiOff = (uint32_t)(1 * TILE_B + bnrow * RSB) + bkb;
    const uint32_t bLoOff = (uint32_t)(2 * TILE_B + bnrow * RSB) + bkb;

    for (;;) {
        if (tid == 0) sh_task = atomicAdd(&g_next, 1);
        __syncthreads();
        const int t = sh_task;
        __syncthreads();          // protect sh_task before next iteration's write
        if (t >= NTASK) return;

        const int lcell = t >> 4;
        const int tile  = t & 15;
        const int mh = tile & 1;                 // M-half (64 rows)
        const int n0 = (tile >> 1) * 64;         // N-slice base (0..448)

        const int2 cc = g_list[lcell];
        const int s = cc.x, k = cc.y;
        const int type = (k < 0) ? 2 : (k == 0 ? 0 : 1);

        // ---- up-front dependency wait (A-source / diagonal only) ----
        const int* pB = nullptr;                 // deferred B-source dep
        if (tid == 0) {
            if (type == 1) {
                const int* p1 = &g_doneH[cellidx(s - 1, k - 1) * 2 + mh];
                while (ld_acq(p1) < 8) __nanosleep(64);
            } else if (type == 2) {
                const int* p = &g_doneH[cellidx(s, s) * 2 + mh];
                while (ld_acq(p) < 8) __nanosleep(64);
            }
        }
        if (type == 1) pB = &g_doneH[cellidx(s, k - 1) * 2 + mh];
        __syncthreads();

        // ---- operand pointers ----
        const bf16 *aH1, *aH2 = nullptr, *wH, *wL;
        const float* bias;
        int ldw, nch;
        size_t rowbase = (size_t)mh * 64 * 512;
        if (type == 0) {
            size_t xb = (size_t)s * 128 * 512 + rowbase;
            aH1 = g_Xhi + xb;
            wH = g_WinHi + (size_t)n0 * 512;  wL = g_WinLo + (size_t)n0 * 512;
            ldw = 512; nch = 8; bias = b_in;
        } else if (type == 1) {
            size_t pa = (size_t)cellidx(s - 1, k - 1) * CELLF + rowbase;
            size_t pb = (size_t)cellidx(s,     k - 1) * CELLF + rowbase;
            aH1 = g_Hhi + pa;
            aH2 = g_Hhi + pb;
            wH = g_Whi + (size_t)n0 * 1024;  wL = g_Wlo + (size_t)n0 * 1024;
            ldw = 1024; nch = 16; bias = b_sani;
        } else {
            size_t pa = (size_t)cellidx(s, s) * CELLF + rowbase;
            aH1 = g_Hhi + pa;
            wH = g_WoutHi + (size_t)n0 * 512;  wL = g_WoutLo + (size_t)n0 * 512;
            ldw = 512; nch = 8; bias = b_out;
        }

        // ---- GEMM: 64x64, K = nch*64, 2-product split (Ahi@Whi + Ahi@Wlo) --
        float acc[2][2][4];
        #pragma unroll
        for (int i = 0; i < 2; ++i)
            #pragma unroll
            for (int j = 0; j < 2; ++j)
                #pragma unroll
                for (int q = 0; q < 4; ++q) acc[i][j][q] = 0.f;

        auto issue = [&](int c) {
            const bf16* ah; int ka;
            if (c < 8) { ah = aH1; ka = c * 64; }
            else       { ah = aH2; ka = (c - 8) * 64; }
            const int kw = c * 64;
            const uint32_t sm = sbase + (uint32_t)(c & (NSTAGE - 1)) * STAGE_B;
            #pragma unroll
            for (int i = 0; i < 2; ++i) {
                const int ch = tid + i * 256;        // 0..511
                const int row = ch >> 3, seg = ch & 7;
                const uint32_t off = (uint32_t)(row * RSB + seg * 16);
                cpa16(sm + 0 * TILE_B + off, ah + (size_t)row * 512 + ka + seg * 8);
                cpa16(sm + 1 * TILE_B + off, wH + (size_t)row * ldw + kw + seg * 8);
                cpa16(sm + 2 * TILE_B + off, wL + (size_t)row * ldw + kw + seg * 8);
            }
            cp_commit();
        };

        issue(0); issue(1); issue(2);

        for (int c = 0; c < nch; ++c) {
            cp_wait2();           // 3 groups outstanding -> group c complete
            // Deferred B-source wait: must complete before issue(8), which
            // happens at the end of chunk BDEP_CHUNK (depth-3 lookahead).
            if (c == BDEP_CHUNK && pB && tid == 0)
                while (ld_acq(pB) < 8) __nanosleep(64);
            __syncthreads();      // one barrier per chunk; issuing below
                                  // targets stage (c-1)%NSTAGE, fully consumed
                                  // before this barrier

            const uint32_t stg = sbase + (uint32_t)(c & (NSTAGE - 1)) * STAGE_B;
            #pragma unroll
            for (int ks = 0; ks < 4; ++ks) {
                const uint32_t kb = stg + ks * 32;   // 16 k-elements = 32 bytes
                uint32_t ah[2][4], bh[4], bl[4];
                LDM4(ah[0][0], ah[0][1], ah[0][2], ah[0][3], kb + aHiOff0);
                LDM4(ah[1][0], ah[1][1], ah[1][2], ah[1][3], kb + aHiOff1);
                LDM4(bh[0], bh[1], bh[2], bh[3], kb + bHiOff);
                LDM4(bl[0], bl[1], bl[2], bl[3], kb + bLoOff);
                // product-major: 4 independent accumulators between reuses
                #pragma unroll
                for (int mi = 0; mi < 2; ++mi)
                    #pragma unroll
                    for (int ni = 0; ni < 2; ++ni)
                        mma16816(acc[mi][ni], ah[mi], bh[ni * 2], bh[ni * 2 + 1]);
                #pragma unroll
                for (int mi = 0; mi < 2; ++mi)
                    #pragma unroll
                    for (int ni = 0; ni < 2; ++ni)
                        mma16816(acc[mi][ni], ah[mi], bl[ni * 2], bl[ni * 2 + 1]);
            }
            if (c + 3 < nch) issue(c + 3);
            else cp_commit();     // empty group keeps wait-depth uniform
        }

        // ---- epilogue ----
        int dstCell = (type == 0) ? cellidx(s, 0) : (type == 1 ? cellidx(s, k) : -1);
        bf16* outHi = (dstCell >= 0) ? g_Hhi + (size_t)dstCell * CELLF : nullptr;
        float* outF = (type == 2) ? g_y + (size_t)s * 128 * 512 : nullptr;

        #pragma unroll
        for (int mi = 0; mi < 2; ++mi) {
            const int r0 = mh * 64 + wm * 32 + mi * 16 + lr;   // row within 128
            #pragma unroll
            for (int ni = 0; ni < 2; ++ni) {
                const int ccol = n0 + wn * 16 + ni * 8 + lc2;
                const float bx = bias[ccol];
                const float by = bias[ccol + 1];
                #pragma unroll
                for (int half = 0; half < 2; ++half) {
                    const int r = r0 + half * 8;
                    const float v0 = acc[mi][ni][half * 2]     + bx;
                    const float v1 = acc[mi][ni][half * 2 + 1] + by;
                    if (outF) {
                        float2 fv; fv.x = v0; fv.y = v1;
                        *reinterpret_cast<float2*>(outF + (size_t)r * 512 + ccol) = fv;
                    } else {
                        __nv_bfloat162 hp;
                        hp.x = __float2bfloat16(v0);
                        hp.y = __float2bfloat16(v1);
                        *reinterpret_cast<__nv_bfloat162*>(outHi + (size_t)r * 512 + ccol) = hp;
                    }
                }
            }
        }

        // ---- signal completion (per cell half) ----
        if (dstCell >= 0) {
            __threadfence();
            __syncthreads();
            if (tid == 0) red_rel(&g_doneH[dstCell * 2 + mh]);
        }
    }
}

// ---------------------------------------------------------------------------
// Prep kernels (weights split to fp32-pair; activations bf16 only)
// ---------------------------------------------------------------------------
__global__ void k_split_sani(const float* __restrict__ src) {
    int i = blockIdx.x * blockDim.x + threadIdx.x;
    float v = src[i];
    bf16 h = __float2bfloat16(v);
    g_Whi[i] = h;
    g_Wlo[i] = __float2bfloat16(v - __bfloat162float(h));
}
__global__ void k_split_in(const float* __restrict__ src) {
    int i = blockIdx.x * blockDim.x + threadIdx.x;
    float v = src[i];
    bf16 h = __float2bfloat16(v);
    g_WinHi[i] = h;
    g_WinLo[i] = __float2bfloat16(v - __bfloat162float(h));
}
__global__ void k_split_out(const float* __restrict__ src) {
    int i = blockIdx.x * blockDim.x + threadIdx.x;
    float v = src[i];
    bf16 h = __float2bfloat16(v);
    g_WoutHi[i] = h;
    g_WoutLo[i] = __float2bfloat16(v - __bfloat162float(h));
}

__global__ void __launch_bounds__(256)
k_gather(const int* __restrict__ labels, const float* __restrict__ emb)
{
    const int r = blockIdx.x;            // r = s*128 + n
    const int n = r & 127, s = r >> 7;
    const float* row = emb + (size_t)labels[n * LL + s] * EE;
    const int e = threadIdx.x * 2;
    float2 v = *reinterpret_cast<const float2*>(row + e);
    __nv_bfloat162 hp;
    hp.x = __float2bfloat16(v.x);
    hp.y = __float2bfloat16(v.y);
    *reinterpret_cast<__nv_bfloat162*>(g_Xhi + (size_t)r * EE + e) = hp;
}

// ---------------------------------------------------------------------------
// Loss (flat row r = s*128+n; reshape(N,L,E) reads flat row n*64+l)
// ---------------------------------------------------------------------------
__global__ void __launch_bounds__(512)
k_loss(const int* __restrict__ labels, const float* __restrict__ emb_table)
{
    __shared__ float red[512];
    const int n = blockIdx.x;
    const int e = threadIdx.x;
    const float* yb = g_y + (size_t)n * LL * EE + e;

    float m = -1e30f;
    #pragma unroll
    for (int l = 0; l < LL; ++l) m = fmaxf(m, yb[(size_t)l * EE]);

    float se = 0.f, dot = 0.f, sume = 0.f;
    #pragma unroll
    for (int l = 0; l < LL; ++l) {
        float yv = yb[(size_t)l * EE];
        float ev = emb_table[(size_t)labels[n * LL + l] * EE + e];
        se   += expf(yv - m);
        dot  += ev * yv;
        sume += ev;
    }
    float lse = m + logf(se);
    red[e] = dot - sume * lse;
    __syncthreads();
    for (int stride = 256; stride > 0; stride >>= 1) {
        if (e < stride) red[e] += red[e + stride];
        __syncthreads();
    }
    if (e == 0) g_part[n] = red[0];
}

__global__ void k_final(float* __restrict__ out)
{
    __shared__ float red[128];
    const int t = threadIdx.x;
    red[t] = g_part[t];
    __syncthreads();
    for (int stride = 64; stride > 0; stride >>= 1) {
        if (t < stride) red[t] += red[t + stride];
        __syncthreads();
    }
    if (t == 0) out[0] = -red[0] / (float)(NB * EE);
}

// ---------------------------------------------------------------------------
extern "C" void kernel_launch(void* const* d_in, const int* in_sizes, int n_in,
                              void* d_out, int out_size)
{
    const int*   labels    = (const int*)  d_in[0];
    const float* emb_table = (const float*)d_in[1];
    const float* W_in      = (const float*)d_in[2];
    const float* b_in      = (const float*)d_in[3];
    const float* W_sani    = (const float*)d_in[4];
    const float* b_sani    = (const float*)d_in[5];
    const float* W_out     = (const float*)d_in[6];
    const float* b_out     = (const float*)d_in[7];

    // Unconditional each call (no static guards; idempotent non-stream API)
    cudaFuncSetAttribute(k_sani, cudaFuncAttributeMaxDynamicSharedMemorySize, GSMEM);

    // Scheduling state reset + task list build
    k_init<<<17, 256>>>();

    // Weight splits + embedding gather
    k_split_sani<<<2048, 256>>>(W_sani);
    k_split_in<<<1024, 256>>>(W_in);
    k_split_out<<<1024, 256>>>(W_out);
    k_gather<<<8192, 256>>>(labels, emb_table);

    // All GEMM work: one persistent dependency-driven kernel (2 CTAs/SM)
    k_sani<<<NCTA, 256, GSMEM>>>(b_in, b_sani, b_out);

    // Loss
    k_loss<<<NB, 512>>>(labels, emb_table);
    k_final<<<1, 128>>>((float*)d_out);
}